// round 1
// baseline (speedup 1.0000x reference)
#include <cuda_runtime.h>

// ---------------- problem constants ----------------
#define NB     8
#define C_     768
#define T_     4096
#define NHEAD  12
#define HD     64
#define M_TOT  32768          // NB * T_
#define HID    3072
#define ADA6   (6*C_)
#define REGSZ  ((size_t)M_TOT * C_)   // one q/k/v region

// ---------------- scratch (device globals; no allocation allowed) ----------------
__device__ float g_silu[NB*C_];
__device__ float g_ada[NB*ADA6];
__device__ float g_bufA[(size_t)M_TOT * C_];     // h / attn_out / h2
__device__ float g_bufB[(size_t)M_TOT * HID];    // qkv regions / h3
__device__ float g_xnew[(size_t)M_TOT * C_];     // x after attention branch

// ---------------- f32x2 helpers ----------------
__device__ __forceinline__ unsigned long long fma2_(unsigned long long a,
                                                    unsigned long long b,
                                                    unsigned long long c) {
    unsigned long long d;
    asm("fma.rn.f32x2 %0, %1, %2, %3;" : "=l"(d) : "l"(a), "l"(b), "l"(c));
    return d;
}
__device__ __forceinline__ unsigned long long pack2_(float x, float y) {
    unsigned long long d;
    asm("mov.b64 %0, {%1, %2};" : "=l"(d) : "f"(x), "f"(y));
    return d;
}
__device__ __forceinline__ float2 unpack2_(unsigned long long a) {
    float lo, hi;
    asm("mov.b64 {%0, %1}, %2;" : "=f"(lo), "=f"(hi) : "l"(a));
    return make_float2(lo, hi);
}

// ---------------- tiny kernels ----------------
__global__ void silu_kernel(const float* __restrict__ c) {
    int i = blockIdx.x * blockDim.x + threadIdx.x;
    if (i < NB*C_) {
        float v = c[i];
        g_silu[i] = v / (1.f + expf(-v));
    }
}

// ada[n, j] = silu(c[n]) . ada_w[j] + ada_b[j]; warp per output
__global__ void ada_kernel(const float* __restrict__ ada_w,
                           const float* __restrict__ ada_b) {
    const int warp = threadIdx.x >> 5, lane = threadIdx.x & 31;
    const int j = blockIdx.x * 4 + warp;        // 0..4607
    const int n = blockIdx.y;
    const float* wrow = ada_w + (size_t)j * C_;
    const float* crow = g_silu + n * C_;
    float s = 0.f;
    for (int k = lane; k < C_; k += 32) s += crow[k] * wrow[k];
    #pragma unroll
    for (int o = 16; o > 0; o >>= 1) s += __shfl_xor_sync(0xffffffffu, s, o);
    if (lane == 0) g_ada[n*ADA6 + j] = s + ada_b[j];
}

// LayerNorm + adaLN modulation.
// SEQ=0: rows are window-layout tokens; gather from x_seq with roll+partition.
// SEQ=1: rows are sequence tokens of g_xnew.
template<int SEQ>
__global__ void ln_mod_kernel(const float* __restrict__ xin) {
    const int t = blockIdx.x;
    const int tid = threadIdx.x;
    int n;
    const float* xr;
    if (SEQ) {
        n = t >> 12;
        xr = g_xnew + (size_t)t * C_;
    } else {
        const int win = t >> 6, tw = t & 63;
        n = win >> 6;
        const int wi = win & 63;
        const int gi = ((wi >> 3) << 3) + (tw >> 3);   // rolled row
        const int gj = ((wi & 7) << 3) + (tw & 7);     // rolled col
        const int i0 = (gi + 4) & 63, j0 = (gj + 4) & 63;  // original coords
        xr = xin + (((size_t)n << 12) + (i0 << 6) + j0) * C_;
    }
    float v0 = xr[tid], v1 = xr[tid + 256], v2 = xr[tid + 512];
    float s  = v0 + v1 + v2;
    float ss = v0*v0 + v1*v1 + v2*v2;
    __shared__ float red[18];
    #pragma unroll
    for (int o = 16; o > 0; o >>= 1) {
        s  += __shfl_xor_sync(0xffffffffu, s,  o);
        ss += __shfl_xor_sync(0xffffffffu, ss, o);
    }
    if ((tid & 31) == 0) { red[tid >> 5] = s; red[8 + (tid >> 5)] = ss; }
    __syncthreads();
    if (tid == 0) {
        float a = 0.f, b = 0.f;
        #pragma unroll
        for (int w = 0; w < 8; w++) { a += red[w]; b += red[8 + w]; }
        const float mean = a * (1.f / 768.f);
        const float var  = b * (1.f / 768.f) - mean * mean;
        red[16] = mean;
        red[17] = rsqrtf(var + 1e-6f);
    }
    __syncthreads();
    const float mean = red[16], rstd = red[17];
    const float* scp = g_ada + n*ADA6 + (SEQ ? 4 : 1) * C_;
    const float* shp = g_ada + n*ADA6 + (SEQ ? 3 : 0) * C_;
    float* outr = g_bufA + (size_t)t * C_;
    float vv[3] = {v0, v1, v2};
    #pragma unroll
    for (int e = 0; e < 3; e++) {
        const int cix = tid + e * 256;
        const float hn = (vv[e] - mean) * rstd;
        outr[cix] = hn * (1.f + scp[cix]) + shp[cix];
    }
}

// ---------------- SGEMM (FFMA2): C[m,n] = sum_k A[m,k] * W[n,k] ----------------
// 128x128x16 tiles, 256 threads, 8x8 per thread (as 8x4 f32x2).
#define BM 128
#define BN 128
#define BK 16

// MODE 0: qkv (N=2304,K=768)  A=bufA -> scatter q/k/v into bufB regions, +bias
// MODE 1: proj (N=768,K=768)  A=bufA -> x_new = x_seq + g_msa*(v+b), unpartition+unroll
// MODE 2: fc1  (N=3072,K=768) A=bufA -> bufB = gelu_tanh(v+b)
// MODE 3: fc2  (N=768,K=3072) A=bufB -> dout = x_new + g_mlp*(v+b)
template<int MODE>
__global__ __launch_bounds__(256, 2) void gemm_kernel(
    const float* __restrict__ Wt, const float* __restrict__ bias,
    const float* __restrict__ x_seq, float* __restrict__ dout)
{
    constexpr int K = (MODE == 3) ? HID : C_;
    const float* A = (MODE == 3) ? (const float*)g_bufB : (const float*)g_bufA;

    __shared__ float As[BK][BM + 4];
    __shared__ float Bs[BK][BN + 4];

    const int tid = threadIdx.x;
    const int bm = blockIdx.y * BM;
    const int bn = blockIdx.x * BN;
    const int lr = tid >> 2;            // 0..63
    const int lc = (tid & 3) << 2;      // 0,4,8,12
    const float* Ap = A  + (size_t)(bm + lr) * K + lc;
    const float* Bp = Wt + (size_t)(bn + lr) * K + lc;
    const int tx = tid & 15, ty = tid >> 4;

    unsigned long long acc[8][4];
    #pragma unroll
    for (int i = 0; i < 8; i++)
        #pragma unroll
        for (int j = 0; j < 4; j++) acc[i][j] = 0ULL;

    for (int k0 = 0; k0 < K; k0 += BK) {
        float4 a0 = *(const float4*)Ap;
        float4 a1 = *(const float4*)(Ap + (size_t)64 * K);
        float4 b0 = *(const float4*)Bp;
        float4 b1 = *(const float4*)(Bp + (size_t)64 * K);
        As[lc+0][lr]    = a0.x; As[lc+1][lr]    = a0.y; As[lc+2][lr]    = a0.z; As[lc+3][lr]    = a0.w;
        As[lc+0][lr+64] = a1.x; As[lc+1][lr+64] = a1.y; As[lc+2][lr+64] = a1.z; As[lc+3][lr+64] = a1.w;
        Bs[lc+0][lr]    = b0.x; Bs[lc+1][lr]    = b0.y; Bs[lc+2][lr]    = b0.z; Bs[lc+3][lr]    = b0.w;
        Bs[lc+0][lr+64] = b1.x; Bs[lc+1][lr+64] = b1.y; Bs[lc+2][lr+64] = b1.z; Bs[lc+3][lr+64] = b1.w;
        __syncthreads();
        #pragma unroll
        for (int kk = 0; kk < BK; kk++) {
            float4 av0 = *(const float4*)&As[kk][ty*8];
            float4 av1 = *(const float4*)&As[kk][ty*8 + 4];
            ulonglong2 bq0 = *(const ulonglong2*)&Bs[kk][tx*8];
            ulonglong2 bq1 = *(const ulonglong2*)&Bs[kk][tx*8 + 4];
            unsigned long long bfr[4] = {bq0.x, bq0.y, bq1.x, bq1.y};
            float afr[8] = {av0.x, av0.y, av0.z, av0.w, av1.x, av1.y, av1.z, av1.w};
            #pragma unroll
            for (int i = 0; i < 8; i++) {
                unsigned long long a2 = pack2_(afr[i], afr[i]);
                #pragma unroll
                for (int j = 0; j < 4; j++)
                    acc[i][j] = fma2_(a2, bfr[j], acc[i][j]);
            }
        }
        __syncthreads();
        Ap += BK; Bp += BK;
    }

    const int row0 = bm + ty*8;
    const int col0 = bn + tx*8;
    #pragma unroll
    for (int i = 0; i < 8; i++) {
        const int row = row0 + i;
        if constexpr (MODE == 0) {
            const int win = row >> 6, tw = row & 63;
            #pragma unroll
            for (int j = 0; j < 4; j++) {
                float2 v = unpack2_(acc[i][j]);
                const int c0 = col0 + j*2;
                const int cg6 = c0 >> 6;
                const int which = cg6 / 12;
                const int head  = cg6 - which * 12;
                const int d0 = c0 & 63;
                float* dst = g_bufB + (size_t)which * REGSZ
                           + (((size_t)(win*NHEAD + head)) << 12) + (tw << 6) + d0;
                v.x += bias[c0]; v.y += bias[c0+1];
                *(float2*)dst = v;
            }
        } else if constexpr (MODE == 1) {
            const int win = row >> 6, tw = row & 63;
            const int n = win >> 6, wi = win & 63;
            const int gi = ((wi >> 3) << 3) + (tw >> 3);
            const int gj = ((wi & 7) << 3) + (tw & 7);
            const int i0 = (gi + 4) & 63, j0 = (gj + 4) & 63;
            const size_t srow = ((size_t)n << 12) + (i0 << 6) + j0;
            const float* xr = x_seq + srow * C_;
            float* dst = g_xnew + srow * C_;
            const float* gp = g_ada + n*ADA6 + 2*C_;
            #pragma unroll
            for (int j = 0; j < 4; j++) {
                float2 v = unpack2_(acc[i][j]);
                const int c0 = col0 + j*2;
                float r0 = xr[c0]   + gp[c0]  * (v.x + bias[c0]);
                float r1 = xr[c0+1] + gp[c0+1]* (v.y + bias[c0+1]);
                *(float2*)(dst + c0) = make_float2(r0, r1);
            }
        } else if constexpr (MODE == 2) {
            float* dst = g_bufB + (size_t)row * HID;
            #pragma unroll
            for (int j = 0; j < 4; j++) {
                float2 v = unpack2_(acc[i][j]);
                const int c0 = col0 + j*2;
                float u0 = v.x + bias[c0], u1 = v.y + bias[c0+1];
                float t0 = tanhf(0.7978845608028654f * (u0 + 0.044715f*u0*u0*u0));
                float t1 = tanhf(0.7978845608028654f * (u1 + 0.044715f*u1*u1*u1));
                *(float2*)(dst + c0) = make_float2(0.5f*u0*(1.f+t0), 0.5f*u1*(1.f+t1));
            }
        } else {
            const int n = row >> 12;
            const float* xr = g_xnew + (size_t)row * C_;
            const float* gp = g_ada + n*ADA6 + 5*C_;
            float* dst = dout + (size_t)row * C_;
            #pragma unroll
            for (int j = 0; j < 4; j++) {
                float2 v = unpack2_(acc[i][j]);
                const int c0 = col0 + j*2;
                float r0 = xr[c0]   + gp[c0]  * (v.x + bias[c0]);
                float r1 = xr[c0+1] + gp[c0+1]* (v.y + bias[c0+1]);
                *(float2*)(dst + c0) = make_float2(r0, r1);
            }
        }
    }
}

// ---------------- window attention: one block per (window, head) ----------------
__global__ __launch_bounds__(128) void attn_kernel() {
    __shared__ float sA[64][65];   // q (scaled), later v
    __shared__ float sB[64][65];   // k, later P (softmax probs)
    const int bid = blockIdx.x;                 // win*12 + head
    const int win = bid / 12, head = bid - win * 12;
    const int tid = threadIdx.x;
    const float* qb = g_bufB + (size_t)bid * 4096;
    const float* kb = qb + REGSZ;
    const float* vb = qb + 2 * REGSZ;

    #pragma unroll
    for (int it = 0; it < 8; it++) {
        const int i = tid + it * 128;           // float4 index 0..1023
        const int r = i >> 4, cq = (i & 15) << 2;
        float4 q4 = *(const float4*)(qb + ((size_t)i << 2));
        float4 k4 = *(const float4*)(kb + ((size_t)i << 2));
        sA[r][cq] = q4.x*0.125f; sA[r][cq+1] = q4.y*0.125f;
        sA[r][cq+2] = q4.z*0.125f; sA[r][cq+3] = q4.w*0.125f;
        sB[r][cq] = k4.x; sB[r][cq+1] = k4.y; sB[r][cq+2] = k4.z; sB[r][cq+3] = k4.w;
    }
    __syncthreads();

    const int rg = tid >> 3, cg = tid & 7;      // rows rg*4.., cols cg*8..
    float acc[4][8];
    #pragma unroll
    for (int mi = 0; mi < 4; mi++)
        #pragma unroll
        for (int ni = 0; ni < 8; ni++) acc[mi][ni] = 0.f;

    #pragma unroll 4
    for (int d = 0; d < 64; d++) {
        float a[4], b[8];
        #pragma unroll
        for (int mi = 0; mi < 4; mi++) a[mi] = sA[rg*4 + mi][d];
        #pragma unroll
        for (int ni = 0; ni < 8; ni++) b[ni] = sB[cg*8 + ni][d];
        #pragma unroll
        for (int mi = 0; mi < 4; mi++)
            #pragma unroll
            for (int ni = 0; ni < 8; ni++) acc[mi][ni] += a[mi] * b[ni];
    }

    // softmax rows (8 lanes per row share via shfl within 8-lane group)
    float p[4][8];
    #pragma unroll
    for (int mi = 0; mi < 4; mi++) {
        float m = acc[mi][0];
        #pragma unroll
        for (int ni = 1; ni < 8; ni++) m = fmaxf(m, acc[mi][ni]);
        #pragma unroll
        for (int o = 4; o > 0; o >>= 1) m = fmaxf(m, __shfl_xor_sync(0xffffffffu, m, o));
        float ssum = 0.f;
        #pragma unroll
        for (int ni = 0; ni < 8; ni++) { p[mi][ni] = expf(acc[mi][ni] - m); ssum += p[mi][ni]; }
        #pragma unroll
        for (int o = 4; o > 0; o >>= 1) ssum += __shfl_xor_sync(0xffffffffu, ssum, o);
        const float inv = 1.f / ssum;
        #pragma unroll
        for (int ni = 0; ni < 8; ni++) p[mi][ni] *= inv;
    }
    __syncthreads();   // everyone done reading q/k

    #pragma unroll
    for (int mi = 0; mi < 4; mi++)
        #pragma unroll
        for (int ni = 0; ni < 8; ni++) sB[rg*4 + mi][cg*8 + ni] = p[mi][ni];
    #pragma unroll
    for (int it = 0; it < 8; it++) {
        const int i = tid + it * 128;
        const int r = i >> 4, cq = (i & 15) << 2;
        float4 v4 = *(const float4*)(vb + ((size_t)i << 2));
        sA[r][cq] = v4.x; sA[r][cq+1] = v4.y; sA[r][cq+2] = v4.z; sA[r][cq+3] = v4.w;
    }
    __syncthreads();

    float o[4][8];
    #pragma unroll
    for (int mi = 0; mi < 4; mi++)
        #pragma unroll
        for (int ni = 0; ni < 8; ni++) o[mi][ni] = 0.f;
    #pragma unroll 4
    for (int cc = 0; cc < 64; cc++) {
        float a[4], b[8];
        #pragma unroll
        for (int mi = 0; mi < 4; mi++) a[mi] = sB[rg*4 + mi][cc];
        #pragma unroll
        for (int ni = 0; ni < 8; ni++) b[ni] = sA[cc][cg*8 + ni];
        #pragma unroll
        for (int mi = 0; mi < 4; mi++)
            #pragma unroll
            for (int ni = 0; ni < 8; ni++) o[mi][ni] += a[mi] * b[ni];
    }

    #pragma unroll
    for (int mi = 0; mi < 4; mi++) {
        const int r = rg*4 + mi;
        float* dst = g_bufA + ((size_t)(win*64 + r)) * C_ + head*64 + cg*8;
        *(float4*)dst       = make_float4(o[mi][0], o[mi][1], o[mi][2], o[mi][3]);
        *(float4*)(dst + 4) = make_float4(o[mi][4], o[mi][5], o[mi][6], o[mi][7]);
    }
}

// ---------------- launcher ----------------
extern "C" void kernel_launch(void* const* d_in, const int* in_sizes, int n_in,
                              void* d_out, int out_size) {
    const float* x_seq  = (const float*)d_in[0];
    const float* c_in   = (const float*)d_in[1];
    const float* qkv_w  = (const float*)d_in[2];
    const float* qkv_b  = (const float*)d_in[3];
    const float* proj_w = (const float*)d_in[4];
    const float* proj_b = (const float*)d_in[5];
    const float* fc1_w  = (const float*)d_in[6];
    const float* fc1_b  = (const float*)d_in[7];
    const float* fc2_w  = (const float*)d_in[8];
    const float* fc2_b  = (const float*)d_in[9];
    const float* ada_w  = (const float*)d_in[10];
    const float* ada_b  = (const float*)d_in[11];
    float* out = (float*)d_out;

    silu_kernel<<<(NB*C_ + 255)/256, 256>>>(c_in);
    ada_kernel<<<dim3(ADA6/4, NB), 128>>>(ada_w, ada_b);
    ln_mod_kernel<0><<<M_TOT, 256>>>(x_seq);
    gemm_kernel<0><<<dim3((3*C_)/BN, M_TOT/BM), 256>>>(qkv_w, qkv_b, nullptr, nullptr);
    attn_kernel<<<512*NHEAD, 128>>>();
    gemm_kernel<1><<<dim3(C_/BN, M_TOT/BM), 256>>>(proj_w, proj_b, x_seq, nullptr);
    ln_mod_kernel<1><<<M_TOT, 256>>>(nullptr);
    gemm_kernel<2><<<dim3(HID/BN, M_TOT/BM), 256>>>(fc1_w, fc1_b, nullptr, nullptr);
    gemm_kernel<3><<<dim3(C_/BN, M_TOT/BM), 256>>>(fc2_w, fc2_b, nullptr, out);
}

// round 3
// speedup vs baseline: 3.4393x; 3.4393x over previous
#include <cuda_runtime.h>
#include <cuda_bf16.h>
#include <cstdint>

// ---------------- problem constants ----------------
#define NB     8
#define C_     768
#define NHEAD  12
#define M_TOT  32768
#define HID    3072
#define ADA6   (6*C_)
#define REGSZ  ((size_t)M_TOT * C_)
#define KC     64            // K per chunk (bf16 -> 128B rows, SW128)

// ---------------- scratch (device globals) ----------------
__device__ float g_silu[NB*C_];
__device__ float g_ada[NB*ADA6];
__device__ float g_qkv[(size_t)3*M_TOT*C_];
__device__ float g_xnew[(size_t)M_TOT*C_];
__device__ __nv_bfloat16 g_actA[(size_t)M_TOT*C_];
__device__ __nv_bfloat16 g_actB[(size_t)M_TOT*HID];
__device__ __nv_bfloat16 g_wqkv[3*C_*C_];
__device__ __nv_bfloat16 g_wproj[C_*C_];
__device__ __nv_bfloat16 g_wfc1[HID*C_];
__device__ __nv_bfloat16 g_wfc2[C_*HID];

// ---------------- ptx helpers ----------------
__device__ __forceinline__ uint32_t smem_u32(const void* p) {
    uint32_t a;
    asm("{ .reg .u64 t; cvta.to.shared.u64 t, %1; cvt.u32.u64 %0, t; }" : "=r"(a) : "l"(p));
    return a;
}
__device__ __forceinline__ void cp16(uint32_t dst, const void* src) {
    asm volatile("cp.async.cg.shared.global [%0], [%1], 16;" :: "r"(dst), "l"(src));
}
__device__ __forceinline__ void cp_commit() { asm volatile("cp.async.commit_group;" ::: "memory"); }
template<int N> __device__ __forceinline__ void cp_wait() {
    asm volatile("cp.async.wait_group %0;" :: "n"(N) : "memory");
}
__device__ __forceinline__ void ldsm4(uint32_t& r0, uint32_t& r1, uint32_t& r2, uint32_t& r3,
                                      uint32_t addr) {
    asm volatile("ldmatrix.sync.aligned.m8n8.x4.shared.b16 {%0,%1,%2,%3}, [%4];"
                 : "=r"(r0), "=r"(r1), "=r"(r2), "=r"(r3) : "r"(addr));
}
__device__ __forceinline__ void mma16816(float& c0, float& c1, float& c2, float& c3,
                                         uint32_t a0, uint32_t a1, uint32_t a2, uint32_t a3,
                                         uint32_t b0, uint32_t b1) {
    asm volatile(
        "mma.sync.aligned.m16n8k16.row.col.f32.bf16.bf16.f32 "
        "{%0,%1,%2,%3}, {%4,%5,%6,%7}, {%8,%9}, {%0,%1,%2,%3};"
        : "+f"(c0), "+f"(c1), "+f"(c2), "+f"(c3)
        : "r"(a0), "r"(a1), "r"(a2), "r"(a3), "r"(b0), "r"(b1));
}

// ---------------- tiny kernels ----------------
__global__ void silu_kernel(const float* __restrict__ c) {
    int i = blockIdx.x * blockDim.x + threadIdx.x;
    if (i < NB*C_) {
        float v = c[i];
        g_silu[i] = v / (1.f + expf(-v));
    }
}

__global__ void ada_kernel(const float* __restrict__ ada_w,
                           const float* __restrict__ ada_b) {
    const int warp = threadIdx.x >> 5, lane = threadIdx.x & 31;
    const int j = blockIdx.x * 4 + warp;
    const int n = blockIdx.y;
    const float* wrow = ada_w + (size_t)j * C_;
    const float* crow = g_silu + n * C_;
    float s = 0.f;
    for (int k = lane; k < C_; k += 32) s += crow[k] * wrow[k];
    #pragma unroll
    for (int o = 16; o > 0; o >>= 1) s += __shfl_xor_sync(0xffffffffu, s, o);
    if (lane == 0) g_ada[n*ADA6 + j] = s + ada_b[j];
}

__global__ void f2bf_kernel(const float* __restrict__ s, __nv_bfloat16* __restrict__ d, int n) {
    int i = (blockIdx.x * blockDim.x + threadIdx.x) * 4;
    if (i < n) {
        float4 v = *(const float4*)(s + i);
        ((__nv_bfloat162*)(d + i))[0] = __floats2bfloat162_rn(v.x, v.y);
        ((__nv_bfloat162*)(d + i))[1] = __floats2bfloat162_rn(v.z, v.w);
    }
}

// LayerNorm + adaLN modulation -> bf16 into g_actA
template<int SEQ>
__global__ void ln_mod_kernel(const float* __restrict__ xin) {
    const int t = blockIdx.x;
    const int tid = threadIdx.x;
    int n;
    const float* xr;
    if (SEQ) {
        n = t >> 12;
        xr = g_xnew + (size_t)t * C_;
    } else {
        const int win = t >> 6, tw = t & 63;
        n = win >> 6;
        const int wi = win & 63;
        const int gi = ((wi >> 3) << 3) + (tw >> 3);
        const int gj = ((wi & 7) << 3) + (tw & 7);
        const int i0 = (gi + 4) & 63, j0 = (gj + 4) & 63;
        xr = xin + (((size_t)n << 12) + (i0 << 6) + j0) * C_;
    }
    float v0 = xr[tid], v1 = xr[tid + 256], v2 = xr[tid + 512];
    float s  = v0 + v1 + v2;
    float ss = v0*v0 + v1*v1 + v2*v2;
    __shared__ float red[18];
    #pragma unroll
    for (int o = 16; o > 0; o >>= 1) {
        s  += __shfl_xor_sync(0xffffffffu, s,  o);
        ss += __shfl_xor_sync(0xffffffffu, ss, o);
    }
    if ((tid & 31) == 0) { red[tid >> 5] = s; red[8 + (tid >> 5)] = ss; }
    __syncthreads();
    if (tid == 0) {
        float a = 0.f, b = 0.f;
        #pragma unroll
        for (int w = 0; w < 8; w++) { a += red[w]; b += red[8 + w]; }
        const float mean = a * (1.f / 768.f);
        const float var  = b * (1.f / 768.f) - mean * mean;
        red[16] = mean;
        red[17] = rsqrtf(var + 1e-6f);
    }
    __syncthreads();
    const float mean = red[16], rstd = red[17];
    const float* scp = g_ada + n*ADA6 + (SEQ ? 4 : 1) * C_;
    const float* shp = g_ada + n*ADA6 + (SEQ ? 3 : 0) * C_;
    __nv_bfloat16* outr = g_actA + (size_t)t * C_;
    float vv[3] = {v0, v1, v2};
    #pragma unroll
    for (int e = 0; e < 3; e++) {
        const int cix = tid + e * 256;
        const float hn = (vv[e] - mean) * rstd;
        outr[cix] = __float2bfloat16(hn * (1.f + scp[cix]) + shp[cix]);
    }
}

// ---------------- HMMA bf16 GEMM: C[m,n] = sum_k A[m,k]*W[n,k] ----------------
// CTA 128x128, K chunks of 64, 3-deep cp.async ring, 8 warps (2x4), warp 64x32.
// MODE 0: qkv  -> scatter q/k/v fp32 + bias
// MODE 1: proj -> g_xnew = x_seq + g*(v+b), unpartition+unroll
// MODE 2: fc1  -> g_actB = bf16(gelu_tanh(v+b))
// MODE 3: fc2  -> dout = g_xnew + g*(v+b)
#define GEMM_SMEM 99328

template<int MODE>
__global__ void __launch_bounds__(256, 2) gemm_tc(
    const float* __restrict__ bias,
    const float* __restrict__ x_seq,
    float* __restrict__ dout)
{
    constexpr int K   = (MODE == 3) ? HID : C_;
    constexpr int NCH = K / KC;
    const __nv_bfloat16* A = (MODE == 3) ? g_actB : g_actA;
    const __nv_bfloat16* W = (MODE == 0) ? g_wqkv : (MODE == 1) ? g_wproj
                           : (MODE == 2) ? g_wfc1 : g_wfc2;

    extern __shared__ char smem[];
    const uint32_t sbase = smem_u32(smem);
    const uint32_t s0 = (sbase + 1023u) & ~1023u;
    const int tid = threadIdx.x;
    const int wid = tid >> 5, lane = tid & 31;
    const int bm = blockIdx.y * 128, bn = blockIdx.x * 128;

    // ---- producer mapping: thread t<128 loads A row t; t>=128 loads B row t-128
    const int ldrow = tid & 127;
    const uint32_t side = (tid >= 128) ? 16384u : 0u;
    const __nv_bfloat16* gsrc = (tid < 128)
        ? (A + (size_t)(bm + ldrow) * K)
        : (W + (size_t)(bn + ldrow) * K);
    uint32_t dof[8];
    #pragma unroll
    for (int s = 0; s < 8; s++) {
        uint32_t o = (uint32_t)ldrow * 128 + s * 16;
        dof[s] = (o ^ ((o >> 3) & 0x70)) + side;
    }
    auto load_chunk = [&](int i) {
        const uint32_t ab = s0 + (uint32_t)(i % 3) * 32768u;
        const __nv_bfloat16* src = gsrc + i * KC;
        #pragma unroll
        for (int s = 0; s < 8; s++) cp16(ab + dof[s], src + s * 8);
        cp_commit();
    };
    load_chunk(0); load_chunk(1); load_chunk(2);

    // ---- consumer mapping (per warp): rows wm*64, cols wn*32
    const int wm = wid >> 2, wn = wid & 3;
    // ldmatrix addresses: row = base + (lane&15), 16B chunk = lane>>4
    uint32_t aOff[4], aXor[4];
    #pragma unroll
    for (int mi = 0; mi < 4; mi++) {
        const int r = wm * 64 + mi * 16 + (lane & 15);
        aOff[mi] = (uint32_t)r * 128 + ((lane >> 4) << 4);
        aXor[mi] = ((uint32_t)(r & 7)) << 4;
    }
    uint32_t bOff[2], bXor[2];
    #pragma unroll
    for (int nj = 0; nj < 2; nj++) {
        const int r = wn * 32 + nj * 16 + (lane & 15);
        bOff[nj] = 16384u + (uint32_t)r * 128 + ((lane >> 4) << 4);
        bXor[nj] = ((uint32_t)(r & 7)) << 4;
    }

    float acc[4][4][4];
    #pragma unroll
    for (int mi = 0; mi < 4; mi++)
        #pragma unroll
        for (int ni = 0; ni < 4; ni++)
            #pragma unroll
            for (int e = 0; e < 4; e++) acc[mi][ni][e] = 0.f;

    for (int i = 0; i < NCH; i++) {
        const int rem = NCH - 1 - i;
        if (rem >= 2)      cp_wait<2>();
        else if (rem == 1) cp_wait<1>();
        else               cp_wait<0>();
        __syncthreads();
        const uint32_t buf = s0 + (uint32_t)(i % 3) * 32768u;
        #pragma unroll
        for (int ks = 0; ks < 4; ks++) {
            const uint32_t kb = (uint32_t)ks * 32;
            uint32_t a_[4][4];
            #pragma unroll
            for (int mi = 0; mi < 4; mi++)
                ldsm4(a_[mi][0], a_[mi][1], a_[mi][2], a_[mi][3],
                      buf + (aOff[mi] & ~0x70u) + (((aOff[mi] & 0x70u) + kb) ^ aXor[mi]));
            uint32_t b_[2][4];
            #pragma unroll
            for (int nj = 0; nj < 2; nj++)
                ldsm4(b_[nj][0], b_[nj][1], b_[nj][2], b_[nj][3],
                      buf + (bOff[nj] & ~0x70u) + (((bOff[nj] & 0x70u) + kb) ^ bXor[nj]));
            #pragma unroll
            for (int mi = 0; mi < 4; mi++) {
                #pragma unroll
                for (int nj = 0; nj < 2; nj++) {
                    mma16816(acc[mi][nj*2+0][0], acc[mi][nj*2+0][1],
                             acc[mi][nj*2+0][2], acc[mi][nj*2+0][3],
                             a_[mi][0], a_[mi][1], a_[mi][2], a_[mi][3],
                             b_[nj][0], b_[nj][2]);
                    mma16816(acc[mi][nj*2+1][0], acc[mi][nj*2+1][1],
                             acc[mi][nj*2+1][2], acc[mi][nj*2+1][3],
                             a_[mi][0], a_[mi][1], a_[mi][2], a_[mi][3],
                             b_[nj][1], b_[nj][3]);
                }
            }
        }
        __syncthreads();
        if (i + 3 < NCH) load_chunk(i + 3);
    }

    // ---------------- epilogue ----------------
    const int rIn = lane >> 2;
    const int cIn = (lane & 3) * 2;
    #pragma unroll
    for (int mi = 0; mi < 4; mi++) {
        #pragma unroll
        for (int h = 0; h < 2; h++) {
            const int row = bm + wm * 64 + mi * 16 + rIn + h * 8;
            if constexpr (MODE == 0) {
                const int win = row >> 6, tw = row & 63;
                #pragma unroll
                for (int ni = 0; ni < 4; ni++) {
                    const int g = bn + wn * 32 + ni * 8 + cIn;
                    const int which = g / 768;
                    const int head = (g >> 6) % 12;
                    const int d0 = g & 63;
                    float* dst = g_qkv + (size_t)which * REGSZ
                               + (((size_t)(win * NHEAD + head)) << 12) + (tw << 6) + d0;
                    float2 v;
                    v.x = acc[mi][ni][h*2+0] + __ldg(bias + g);
                    v.y = acc[mi][ni][h*2+1] + __ldg(bias + g + 1);
                    *(float2*)dst = v;
                }
            } else if constexpr (MODE == 1) {
                const int win = row >> 6, tw = row & 63;
                const int n = win >> 6, wi = win & 63;
                const int gi = ((wi >> 3) << 3) + (tw >> 3);
                const int gj = ((wi & 7) << 3) + (tw & 7);
                const int i0 = (gi + 4) & 63, j0 = (gj + 4) & 63;
                const size_t srow = ((size_t)n << 12) + (i0 << 6) + j0;
                const float* xr = x_seq + srow * C_;
                float* dst = g_xnew + srow * C_;
                const float* gp = g_ada + n * ADA6 + 2 * C_;
                #pragma unroll
                for (int ni = 0; ni < 4; ni++) {
                    const int g = bn + wn * 32 + ni * 8 + cIn;
                    float2 v;
                    v.x = xr[g]   + gp[g]   * (acc[mi][ni][h*2+0] + __ldg(bias + g));
                    v.y = xr[g+1] + gp[g+1] * (acc[mi][ni][h*2+1] + __ldg(bias + g + 1));
                    *(float2*)(dst + g) = v;
                }
            } else if constexpr (MODE == 2) {
                __nv_bfloat16* dst = g_actB + (size_t)row * HID;
                #pragma unroll
                for (int ni = 0; ni < 4; ni++) {
                    const int g = bn + wn * 32 + ni * 8 + cIn;
                    float u0 = acc[mi][ni][h*2+0] + __ldg(bias + g);
                    float u1 = acc[mi][ni][h*2+1] + __ldg(bias + g + 1);
                    float t0 = tanhf(0.7978845608028654f * (u0 + 0.044715f * u0 * u0 * u0));
                    float t1 = tanhf(0.7978845608028654f * (u1 + 0.044715f * u1 * u1 * u1));
                    *(__nv_bfloat162*)(dst + g) =
                        __floats2bfloat162_rn(0.5f * u0 * (1.f + t0), 0.5f * u1 * (1.f + t1));
                }
            } else {
                const int n = row >> 12;
                const float* xr = g_xnew + (size_t)row * C_;
                const float* gp = g_ada + n * ADA6 + 5 * C_;
                float* dst = dout + (size_t)row * C_;
                #pragma unroll
                for (int ni = 0; ni < 4; ni++) {
                    const int g = bn + wn * 32 + ni * 8 + cIn;
                    float2 v;
                    v.x = xr[g]   + gp[g]   * (acc[mi][ni][h*2+0] + __ldg(bias + g));
                    v.y = xr[g+1] + gp[g+1] * (acc[mi][ni][h*2+1] + __ldg(bias + g + 1));
                    *(float2*)(dst + g) = v;
                }
            }
        }
    }
}

// ---------------- window attention: one block per (window, head) ----------------
__global__ void __launch_bounds__(128) attn_kernel() {
    __shared__ float sA[64][65];
    __shared__ float sB[64][65];
    const int bid = blockIdx.x;
    const int win = bid / 12, head = bid - win * 12;
    const int tid = threadIdx.x;
    const float* qb = g_qkv + (size_t)bid * 4096;
    const float* kb = qb + REGSZ;
    const float* vb = qb + 2 * REGSZ;

    #pragma unroll
    for (int it = 0; it < 8; it++) {
        const int i = tid + it * 128;
        const int r = i >> 4, cq = (i & 15) << 2;
        float4 q4 = *(const float4*)(qb + ((size_t)i << 2));
        float4 k4 = *(const float4*)(kb + ((size_t)i << 2));
        sA[r][cq] = q4.x*0.125f; sA[r][cq+1] = q4.y*0.125f;
        sA[r][cq+2] = q4.z*0.125f; sA[r][cq+3] = q4.w*0.125f;
        sB[r][cq] = k4.x; sB[r][cq+1] = k4.y; sB[r][cq+2] = k4.z; sB[r][cq+3] = k4.w;
    }
    __syncthreads();

    const int rg = tid >> 3, cg = tid & 7;
    float acc[4][8];
    #pragma unroll
    for (int mi = 0; mi < 4; mi++)
        #pragma unroll
        for (int ni = 0; ni < 8; ni++) acc[mi][ni] = 0.f;

    #pragma unroll 4
    for (int d = 0; d < 64; d++) {
        float a[4], b[8];
        #pragma unroll
        for (int mi = 0; mi < 4; mi++) a[mi] = sA[rg*4 + mi][d];
        #pragma unroll
        for (int ni = 0; ni < 8; ni++) b[ni] = sB[cg*8 + ni][d];
        #pragma unroll
        for (int mi = 0; mi < 4; mi++)
            #pragma unroll
            for (int ni = 0; ni < 8; ni++) acc[mi][ni] += a[mi] * b[ni];
    }

    float p[4][8];
    #pragma unroll
    for (int mi = 0; mi < 4; mi++) {
        float m = acc[mi][0];
        #pragma unroll
        for (int ni = 1; ni < 8; ni++) m = fmaxf(m, acc[mi][ni]);
        #pragma unroll
        for (int o = 4; o > 0; o >>= 1) m = fmaxf(m, __shfl_xor_sync(0xffffffffu, m, o));
        float ssum = 0.f;
        #pragma unroll
        for (int ni = 0; ni < 8; ni++) { p[mi][ni] = expf(acc[mi][ni] - m); ssum += p[mi][ni]; }
        #pragma unroll
        for (int o = 4; o > 0; o >>= 1) ssum += __shfl_xor_sync(0xffffffffu, ssum, o);
        const float inv = 1.f / ssum;
        #pragma unroll
        for (int ni = 0; ni < 8; ni++) p[mi][ni] *= inv;
    }
    __syncthreads();

    #pragma unroll
    for (int mi = 0; mi < 4; mi++)
        #pragma unroll
        for (int ni = 0; ni < 8; ni++) sB[rg*4 + mi][cg*8 + ni] = p[mi][ni];
    #pragma unroll
    for (int it = 0; it < 8; it++) {
        const int i = tid + it * 128;
        const int r = i >> 4, cq = (i & 15) << 2;
        float4 v4 = *(const float4*)(vb + ((size_t)i << 2));
        sA[r][cq] = v4.x; sA[r][cq+1] = v4.y; sA[r][cq+2] = v4.z; sA[r][cq+3] = v4.w;
    }
    __syncthreads();

    float o[4][8];
    #pragma unroll
    for (int mi = 0; mi < 4; mi++)
        #pragma unroll
        for (int ni = 0; ni < 8; ni++) o[mi][ni] = 0.f;
    #pragma unroll 4
    for (int cc = 0; cc < 64; cc++) {
        float a[4], b[8];
        #pragma unroll
        for (int mi = 0; mi < 4; mi++) a[mi] = sB[rg*4 + mi][cc];
        #pragma unroll
        for (int ni = 0; ni < 8; ni++) b[ni] = sA[cc][cg*8 + ni];
        #pragma unroll
        for (int mi = 0; mi < 4; mi++)
            #pragma unroll
            for (int ni = 0; ni < 8; ni++) o[mi][ni] += a[mi] * b[ni];
    }

    #pragma unroll
    for (int mi = 0; mi < 4; mi++) {
        const int r = rg*4 + mi;
        __nv_bfloat16* dst = g_actA + ((size_t)(win*64 + r)) * C_ + head*64 + cg*8;
        ((__nv_bfloat162*)dst)[0] = __floats2bfloat162_rn(o[mi][0], o[mi][1]);
        ((__nv_bfloat162*)dst)[1] = __floats2bfloat162_rn(o[mi][2], o[mi][3]);
        ((__nv_bfloat162*)dst)[2] = __floats2bfloat162_rn(o[mi][4], o[mi][5]);
        ((__nv_bfloat162*)dst)[3] = __floats2bfloat162_rn(o[mi][6], o[mi][7]);
    }
}

// ---------------- launcher ----------------
extern "C" void kernel_launch(void* const* d_in, const int* in_sizes, int n_in,
                              void* d_out, int out_size) {
    const float* x_seq  = (const float*)d_in[0];
    const float* c_in   = (const float*)d_in[1];
    const float* qkv_w  = (const float*)d_in[2];
    const float* qkv_b  = (const float*)d_in[3];
    const float* proj_w = (const float*)d_in[4];
    const float* proj_b = (const float*)d_in[5];
    const float* fc1_w  = (const float*)d_in[6];
    const float* fc1_b  = (const float*)d_in[7];
    const float* fc2_w  = (const float*)d_in[8];
    const float* fc2_b  = (const float*)d_in[9];
    const float* ada_w  = (const float*)d_in[10];
    const float* ada_b  = (const float*)d_in[11];
    float* out = (float*)d_out;

    cudaFuncSetAttribute(gemm_tc<0>, cudaFuncAttributeMaxDynamicSharedMemorySize, GEMM_SMEM);
    cudaFuncSetAttribute(gemm_tc<1>, cudaFuncAttributeMaxDynamicSharedMemorySize, GEMM_SMEM);
    cudaFuncSetAttribute(gemm_tc<2>, cudaFuncAttributeMaxDynamicSharedMemorySize, GEMM_SMEM);
    cudaFuncSetAttribute(gemm_tc<3>, cudaFuncAttributeMaxDynamicSharedMemorySize, GEMM_SMEM);

    __nv_bfloat16 *wq, *wp, *w1, *w2;
    cudaGetSymbolAddress((void**)&wq, g_wqkv);
    cudaGetSymbolAddress((void**)&wp, g_wproj);
    cudaGetSymbolAddress((void**)&w1, g_wfc1);
    cudaGetSymbolAddress((void**)&w2, g_wfc2);

    f2bf_kernel<<<(3*C_*C_/4 + 255)/256, 256>>>(qkv_w,  wq, 3*C_*C_);
    f2bf_kernel<<<(C_*C_/4   + 255)/256, 256>>>(proj_w, wp, C_*C_);
    f2bf_kernel<<<(HID*C_/4  + 255)/256, 256>>>(fc1_w,  w1, HID*C_);
    f2bf_kernel<<<(C_*HID/4  + 255)/256, 256>>>(fc2_w,  w2, C_*HID);

    silu_kernel<<<(NB*C_ + 255)/256, 256>>>(c_in);
    ada_kernel<<<dim3(ADA6/4, NB), 128>>>(ada_w, ada_b);

    ln_mod_kernel<0><<<M_TOT, 256>>>(x_seq);
    gemm_tc<0><<<dim3(18, 256), 256, GEMM_SMEM>>>(qkv_b, nullptr, nullptr);
    attn_kernel<<<512*NHEAD, 128>>>();
    gemm_tc<1><<<dim3(6, 256), 256, GEMM_SMEM>>>(proj_b, x_seq, nullptr);
    ln_mod_kernel<1><<<M_TOT, 256>>>(nullptr);
    gemm_tc<2><<<dim3(24, 256), 256, GEMM_SMEM>>>(fc1_b, nullptr, nullptr);
    gemm_tc<3><<<dim3(6, 256), 256, GEMM_SMEM>>>(fc2_b, nullptr, out);
}

// round 4
// speedup vs baseline: 3.6827x; 1.0708x over previous
#include <cuda_runtime.h>
#include <cuda_bf16.h>
#include <cstdint>

// ---------------- problem constants ----------------
#define NB     8
#define C_     768
#define NHEAD  12
#define M_TOT  32768
#define HID    3072
#define ADA6   (6*C_)
#define REGSZ  ((size_t)M_TOT * C_)
#define KC     64            // K per chunk (bf16 -> 128B rows, SW128)

// ---------------- scratch (device globals) ----------------
__device__ float g_silu[NB*C_];
__device__ float g_ada[NB*ADA6];
__device__ __nv_bfloat16 g_qkv[(size_t)3*M_TOT*C_];   // q/k/v regions, (win,head,tw,d)
__device__ float g_xnew[(size_t)M_TOT*C_];
__device__ __nv_bfloat16 g_actA[(size_t)M_TOT*C_];
__device__ __nv_bfloat16 g_actB[(size_t)M_TOT*HID];
__device__ __nv_bfloat16 g_wqkv[3*C_*C_];
__device__ __nv_bfloat16 g_wproj[C_*C_];
__device__ __nv_bfloat16 g_wfc1[HID*C_];
__device__ __nv_bfloat16 g_wfc2[C_*HID];

// ---------------- ptx helpers ----------------
__device__ __forceinline__ uint32_t smem_u32(const void* p) {
    uint32_t a;
    asm("{ .reg .u64 t; cvta.to.shared.u64 t, %1; cvt.u32.u64 %0, t; }" : "=r"(a) : "l"(p));
    return a;
}
__device__ __forceinline__ void cp16(uint32_t dst, const void* src) {
    asm volatile("cp.async.cg.shared.global [%0], [%1], 16;" :: "r"(dst), "l"(src));
}
__device__ __forceinline__ void cp_commit() { asm volatile("cp.async.commit_group;" ::: "memory"); }
template<int N> __device__ __forceinline__ void cp_wait() {
    asm volatile("cp.async.wait_group %0;" :: "n"(N) : "memory");
}
__device__ __forceinline__ void ldsm4(uint32_t& r0, uint32_t& r1, uint32_t& r2, uint32_t& r3,
                                      uint32_t addr) {
    asm volatile("ldmatrix.sync.aligned.m8n8.x4.shared.b16 {%0,%1,%2,%3}, [%4];"
                 : "=r"(r0), "=r"(r1), "=r"(r2), "=r"(r3) : "r"(addr));
}
__device__ __forceinline__ void ldsm4t(uint32_t& r0, uint32_t& r1, uint32_t& r2, uint32_t& r3,
                                       uint32_t addr) {
    asm volatile("ldmatrix.sync.aligned.m8n8.x4.trans.shared.b16 {%0,%1,%2,%3}, [%4];"
                 : "=r"(r0), "=r"(r1), "=r"(r2), "=r"(r3) : "r"(addr));
}
__device__ __forceinline__ void mma16816(float* c,
                                         const uint32_t* a,
                                         uint32_t b0, uint32_t b1) {
    asm volatile(
        "mma.sync.aligned.m16n8k16.row.col.f32.bf16.bf16.f32 "
        "{%0,%1,%2,%3}, {%4,%5,%6,%7}, {%8,%9}, {%0,%1,%2,%3};"
        : "+f"(c[0]), "+f"(c[1]), "+f"(c[2]), "+f"(c[3])
        : "r"(a[0]), "r"(a[1]), "r"(a[2]), "r"(a[3]), "r"(b0), "r"(b1));
}
__device__ __forceinline__ uint32_t swz(uint32_t o) { return o ^ ((o >> 3) & 0x70); }
__device__ __forceinline__ uint32_t packbf(float x, float y) {
    __nv_bfloat162 h = __floats2bfloat162_rn(x, y);
    return *(uint32_t*)&h;
}

// ---------------- tiny kernels ----------------
__global__ void silu_kernel(const float* __restrict__ c) {
    int i = blockIdx.x * blockDim.x + threadIdx.x;
    if (i < NB*C_) {
        float v = c[i];
        g_silu[i] = v / (1.f + expf(-v));
    }
}

__global__ void ada_kernel(const float* __restrict__ ada_w,
                           const float* __restrict__ ada_b) {
    const int warp = threadIdx.x >> 5, lane = threadIdx.x & 31;
    const int j = blockIdx.x * 4 + warp;
    const int n = blockIdx.y;
    const float* wrow = ada_w + (size_t)j * C_;
    const float* crow = g_silu + n * C_;
    float s = 0.f;
    for (int k = lane; k < C_; k += 32) s += crow[k] * wrow[k];
    #pragma unroll
    for (int o = 16; o > 0; o >>= 1) s += __shfl_xor_sync(0xffffffffu, s, o);
    if (lane == 0) g_ada[n*ADA6 + j] = s + ada_b[j];
}

__global__ void f2bf_kernel(const float* __restrict__ s, __nv_bfloat16* __restrict__ d, int n) {
    int i = (blockIdx.x * blockDim.x + threadIdx.x) * 4;
    if (i < n) {
        float4 v = *(const float4*)(s + i);
        ((__nv_bfloat162*)(d + i))[0] = __floats2bfloat162_rn(v.x, v.y);
        ((__nv_bfloat162*)(d + i))[1] = __floats2bfloat162_rn(v.z, v.w);
    }
}

// LayerNorm + adaLN modulation -> bf16 into g_actA
template<int SEQ>
__global__ void ln_mod_kernel(const float* __restrict__ xin) {
    const int t = blockIdx.x;
    const int tid = threadIdx.x;
    int n;
    const float* xr;
    if (SEQ) {
        n = t >> 12;
        xr = g_xnew + (size_t)t * C_;
    } else {
        const int win = t >> 6, tw = t & 63;
        n = win >> 6;
        const int wi = win & 63;
        const int gi = ((wi >> 3) << 3) + (tw >> 3);
        const int gj = ((wi & 7) << 3) + (tw & 7);
        const int i0 = (gi + 4) & 63, j0 = (gj + 4) & 63;
        xr = xin + (((size_t)n << 12) + (i0 << 6) + j0) * C_;
    }
    float v0 = xr[tid], v1 = xr[tid + 256], v2 = xr[tid + 512];
    float s  = v0 + v1 + v2;
    float ss = v0*v0 + v1*v1 + v2*v2;
    __shared__ float red[18];
    #pragma unroll
    for (int o = 16; o > 0; o >>= 1) {
        s  += __shfl_xor_sync(0xffffffffu, s,  o);
        ss += __shfl_xor_sync(0xffffffffu, ss, o);
    }
    if ((tid & 31) == 0) { red[tid >> 5] = s; red[8 + (tid >> 5)] = ss; }
    __syncthreads();
    if (tid == 0) {
        float a = 0.f, b = 0.f;
        #pragma unroll
        for (int w = 0; w < 8; w++) { a += red[w]; b += red[8 + w]; }
        const float mean = a * (1.f / 768.f);
        const float var  = b * (1.f / 768.f) - mean * mean;
        red[16] = mean;
        red[17] = rsqrtf(var + 1e-6f);
    }
    __syncthreads();
    const float mean = red[16], rstd = red[17];
    const float* scp = g_ada + n*ADA6 + (SEQ ? 4 : 1) * C_;
    const float* shp = g_ada + n*ADA6 + (SEQ ? 3 : 0) * C_;
    __nv_bfloat16* outr = g_actA + (size_t)t * C_;
    float vv[3] = {v0, v1, v2};
    #pragma unroll
    for (int e = 0; e < 3; e++) {
        const int cix = tid + e * 256;
        const float hn = (vv[e] - mean) * rstd;
        outr[cix] = __float2bfloat16(hn * (1.f + scp[cix]) + shp[cix]);
    }
}

// ---------------- HMMA bf16 GEMM: C[m,n] = sum_k A[m,k]*W[n,k] ----------------
// CTA 128x128, K chunks of 64, 3-buffer cp.async ring (2 ahead, 1 sync/chunk),
// 8 warps (2x4), warp tile 64x32.
#define GEMM_SMEM 99328

template<int MODE>
__global__ void __launch_bounds__(256, 2) gemm_tc(
    const float* __restrict__ bias,
    const float* __restrict__ x_seq,
    float* __restrict__ dout)
{
    constexpr int K   = (MODE == 3) ? HID : C_;
    constexpr int NCH = K / KC;
    const __nv_bfloat16* A = (MODE == 3) ? g_actB : g_actA;
    const __nv_bfloat16* W = (MODE == 0) ? g_wqkv : (MODE == 1) ? g_wproj
                           : (MODE == 2) ? g_wfc1 : g_wfc2;

    extern __shared__ char smem[];
    const uint32_t sbase = smem_u32(smem);
    const uint32_t s0 = (sbase + 1023u) & ~1023u;
    const int tid = threadIdx.x;
    const int wid = tid >> 5, lane = tid & 31;
    const int bm = blockIdx.y * 128, bn = blockIdx.x * 128;

    const int ldrow = tid & 127;
    const uint32_t side = (tid >= 128) ? 16384u : 0u;
    const __nv_bfloat16* gsrc = (tid < 128)
        ? (A + (size_t)(bm + ldrow) * K)
        : (W + (size_t)(bn + ldrow) * K);
    uint32_t dof[8];
    #pragma unroll
    for (int s = 0; s < 8; s++) {
        uint32_t o = (uint32_t)ldrow * 128 + s * 16;
        dof[s] = (o ^ ((o >> 3) & 0x70)) + side;
    }
    auto load_chunk = [&](int i) {
        const uint32_t ab = s0 + (uint32_t)(i % 3) * 32768u;
        const __nv_bfloat16* src = gsrc + i * KC;
        #pragma unroll
        for (int s = 0; s < 8; s++) cp16(ab + dof[s], src + s * 8);
        cp_commit();
    };
    load_chunk(0); load_chunk(1);

    const int wm = wid >> 2, wn = wid & 3;
    uint32_t aOff[4], aXor[4];
    #pragma unroll
    for (int mi = 0; mi < 4; mi++) {
        const int r = wm * 64 + mi * 16 + (lane & 15);
        aOff[mi] = (uint32_t)r * 128 + ((lane >> 4) << 4);
        aXor[mi] = ((uint32_t)(r & 7)) << 4;
    }
    uint32_t bOff[2], bXor[2];
    #pragma unroll
    for (int nj = 0; nj < 2; nj++) {
        const int r = wn * 32 + nj * 16 + (lane & 15);
        bOff[nj] = 16384u + (uint32_t)r * 128 + ((lane >> 4) << 4);
        bXor[nj] = ((uint32_t)(r & 7)) << 4;
    }

    float acc[4][4][4];
    #pragma unroll
    for (int mi = 0; mi < 4; mi++)
        #pragma unroll
        for (int ni = 0; ni < 4; ni++)
            #pragma unroll
            for (int e = 0; e < 4; e++) acc[mi][ni][e] = 0.f;

    for (int i = 0; i < NCH; i++) {
        if (i < NCH - 1) cp_wait<1>(); else cp_wait<0>();
        __syncthreads();
        if (i + 2 < NCH) load_chunk(i + 2);
        const uint32_t buf = s0 + (uint32_t)(i % 3) * 32768u;
        #pragma unroll
        for (int ks = 0; ks < 4; ks++) {
            const uint32_t kb = (uint32_t)ks * 32;
            uint32_t a_[4][4];
            #pragma unroll
            for (int mi = 0; mi < 4; mi++)
                ldsm4(a_[mi][0], a_[mi][1], a_[mi][2], a_[mi][3],
                      buf + (aOff[mi] & ~0x70u) + (((aOff[mi] & 0x70u) + kb) ^ aXor[mi]));
            uint32_t b_[2][4];
            #pragma unroll
            for (int nj = 0; nj < 2; nj++)
                ldsm4(b_[nj][0], b_[nj][1], b_[nj][2], b_[nj][3],
                      buf + (bOff[nj] & ~0x70u) + (((bOff[nj] & 0x70u) + kb) ^ bXor[nj]));
            #pragma unroll
            for (int mi = 0; mi < 4; mi++) {
                #pragma unroll
                for (int nj = 0; nj < 2; nj++) {
                    mma16816(acc[mi][nj*2+0], a_[mi], b_[nj][0], b_[nj][2]);
                    mma16816(acc[mi][nj*2+1], a_[mi], b_[nj][1], b_[nj][3]);
                }
            }
        }
    }

    // ---------------- epilogue ----------------
    const int rIn = lane >> 2;
    const int cIn = (lane & 3) * 2;
    #pragma unroll
    for (int mi = 0; mi < 4; mi++) {
        #pragma unroll
        for (int h = 0; h < 2; h++) {
            const int row = bm + wm * 64 + mi * 16 + rIn + h * 8;
            if constexpr (MODE == 0) {
                const int win = row >> 6, tw = row & 63;
                #pragma unroll
                for (int ni = 0; ni < 4; ni++) {
                    const int g = bn + wn * 32 + ni * 8 + cIn;
                    const int which = g / 768;
                    const int head = (g >> 6) % 12;
                    const int d0 = g & 63;
                    __nv_bfloat16* dst = g_qkv + (size_t)which * REGSZ
                               + (((size_t)(win * NHEAD + head)) << 12) + (tw << 6) + d0;
                    *(__nv_bfloat162*)dst = __floats2bfloat162_rn(
                        acc[mi][ni][h*2+0] + __ldg(bias + g),
                        acc[mi][ni][h*2+1] + __ldg(bias + g + 1));
                }
            } else if constexpr (MODE == 1) {
                const int win = row >> 6, tw = row & 63;
                const int n = win >> 6, wi = win & 63;
                const int gi = ((wi >> 3) << 3) + (tw >> 3);
                const int gj = ((wi & 7) << 3) + (tw & 7);
                const int i0 = (gi + 4) & 63, j0 = (gj + 4) & 63;
                const size_t srow = ((size_t)n << 12) + (i0 << 6) + j0;
                const float* xr = x_seq + srow * C_;
                float* dst = g_xnew + srow * C_;
                const float* gp = g_ada + n * ADA6 + 2 * C_;
                #pragma unroll
                for (int ni = 0; ni < 4; ni++) {
                    const int g = bn + wn * 32 + ni * 8 + cIn;
                    float2 v;
                    v.x = xr[g]   + gp[g]   * (acc[mi][ni][h*2+0] + __ldg(bias + g));
                    v.y = xr[g+1] + gp[g+1] * (acc[mi][ni][h*2+1] + __ldg(bias + g + 1));
                    *(float2*)(dst + g) = v;
                }
            } else if constexpr (MODE == 2) {
                __nv_bfloat16* dst = g_actB + (size_t)row * HID;
                #pragma unroll
                for (int ni = 0; ni < 4; ni++) {
                    const int g = bn + wn * 32 + ni * 8 + cIn;
                    float u0 = acc[mi][ni][h*2+0] + __ldg(bias + g);
                    float u1 = acc[mi][ni][h*2+1] + __ldg(bias + g + 1);
                    float t0 = tanhf(0.7978845608028654f * (u0 + 0.044715f * u0 * u0 * u0));
                    float t1 = tanhf(0.7978845608028654f * (u1 + 0.044715f * u1 * u1 * u1));
                    *(__nv_bfloat162*)(dst + g) =
                        __floats2bfloat162_rn(0.5f * u0 * (1.f + t0), 0.5f * u1 * (1.f + t1));
                }
            } else {
                const int n = row >> 12;
                const float* xr = g_xnew + (size_t)row * C_;
                const float* gp = g_ada + n * ADA6 + 5 * C_;
                float* dst = dout + (size_t)row * C_;
                #pragma unroll
                for (int ni = 0; ni < 4; ni++) {
                    const int g = bn + wn * 32 + ni * 8 + cIn;
                    float2 v;
                    v.x = xr[g]   + gp[g]   * (acc[mi][ni][h*2+0] + __ldg(bias + g));
                    v.y = xr[g+1] + gp[g+1] * (acc[mi][ni][h*2+1] + __ldg(bias + g + 1));
                    *(float2*)(dst + g) = v;
                }
            }
        }
    }
}

// ---------------- HMMA window attention: one block per (window, head) ----------------
// 4 warps; warp w owns rows 16w..16w+15. S = (Q K^T)/8, softmax rows, O = P V.
__global__ void __launch_bounds__(128) attn_hmma() {
    __shared__ __align__(1024) __nv_bfloat16 sm[3 * 4096];   // q | k | v, SW128 rows
    const uint32_t sb = smem_u32(sm);
    const int bid = blockIdx.x;                 // win*12 + head
    const int win = bid / 12, head = bid - 12 * win;
    const int tid = threadIdx.x, wid = tid >> 5, lane = tid & 31;
    const __nv_bfloat16* qb = g_qkv + (size_t)bid * 4096;
    const __nv_bfloat16* kb = qb + REGSZ;
    const __nv_bfloat16* vb = qb + 2 * REGSZ;

    // load q,k (full rows by half the CTA each) and v (half-rows by all)
    {
        const int r = tid & 63;
        const __nv_bfloat16* src = ((tid < 64) ? qb : kb) + r * 64;
        const uint32_t base = sb + ((tid < 64) ? 0u : 8192u);
        #pragma unroll
        for (int s = 0; s < 8; s++)
            cp16(base + swz((uint32_t)r * 128 + s * 16), src + s * 8);
        const int vr = tid >> 1;
        const int c0 = (tid & 1) * 4;
        #pragma unroll
        for (int s = 0; s < 4; s++)
            cp16(sb + 16384u + swz((uint32_t)vr * 128 + (c0 + s) * 16), vb + vr * 64 + (c0 + s) * 8);
    }
    cp_commit();
    cp_wait<0>();
    __syncthreads();

    const int lr = lane & 15, lc = lane >> 4;

    // ---- S = Q K^T (64x64 per block; m16 x n64 per warp)
    uint32_t aF[4][4];
    #pragma unroll
    for (int ks = 0; ks < 4; ks++)
        ldsm4(aF[ks][0], aF[ks][1], aF[ks][2], aF[ks][3],
              sb + swz((uint32_t)(16 * wid + lr) * 128 + lc * 16 + ks * 32));

    float S[8][4];
    #pragma unroll
    for (int f = 0; f < 8; f++)
        #pragma unroll
        for (int e = 0; e < 4; e++) S[f][e] = 0.f;

    #pragma unroll
    for (int nj = 0; nj < 4; nj++) {
        #pragma unroll
        for (int ks = 0; ks < 4; ks++) {
            uint32_t b0, b1, b2, b3;
            ldsm4(b0, b1, b2, b3,
                  sb + 8192u + swz((uint32_t)(nj * 16 + lr) * 128 + lc * 16 + ks * 32));
            mma16816(S[2*nj+0], aF[ks], b0, b2);
            mma16816(S[2*nj+1], aF[ks], b1, b3);
        }
    }

    // ---- softmax over full rows (thread-row pair r, r+8; cols spread over lane&3 group)
    float mx0 = -1e30f, mx1 = -1e30f;
    #pragma unroll
    for (int f = 0; f < 8; f++) {
        #pragma unroll
        for (int e = 0; e < 4; e++) S[f][e] *= 0.125f;
        mx0 = fmaxf(mx0, fmaxf(S[f][0], S[f][1]));
        mx1 = fmaxf(mx1, fmaxf(S[f][2], S[f][3]));
    }
    mx0 = fmaxf(mx0, __shfl_xor_sync(0xffffffffu, mx0, 1));
    mx0 = fmaxf(mx0, __shfl_xor_sync(0xffffffffu, mx0, 2));
    mx1 = fmaxf(mx1, __shfl_xor_sync(0xffffffffu, mx1, 1));
    mx1 = fmaxf(mx1, __shfl_xor_sync(0xffffffffu, mx1, 2));
    float sm0 = 0.f, sm1 = 0.f;
    #pragma unroll
    for (int f = 0; f < 8; f++) {
        S[f][0] = __expf(S[f][0] - mx0); sm0 += S[f][0];
        S[f][1] = __expf(S[f][1] - mx0); sm0 += S[f][1];
        S[f][2] = __expf(S[f][2] - mx1); sm1 += S[f][2];
        S[f][3] = __expf(S[f][3] - mx1); sm1 += S[f][3];
    }
    sm0 += __shfl_xor_sync(0xffffffffu, sm0, 1);
    sm0 += __shfl_xor_sync(0xffffffffu, sm0, 2);
    sm1 += __shfl_xor_sync(0xffffffffu, sm1, 1);
    sm1 += __shfl_xor_sync(0xffffffffu, sm1, 2);
    const float iv0 = 1.f / sm0, iv1 = 1.f / sm1;
    #pragma unroll
    for (int f = 0; f < 8; f++) {
        S[f][0] *= iv0; S[f][1] *= iv0; S[f][2] *= iv1; S[f][3] *= iv1;
    }

    // ---- pack P into A-fragments (acc layout == a-frag layout)
    uint32_t aP[4][4];
    #pragma unroll
    for (int ks = 0; ks < 4; ks++) {
        aP[ks][0] = packbf(S[2*ks+0][0], S[2*ks+0][1]);
        aP[ks][1] = packbf(S[2*ks+0][2], S[2*ks+0][3]);
        aP[ks][2] = packbf(S[2*ks+1][0], S[2*ks+1][1]);
        aP[ks][3] = packbf(S[2*ks+1][2], S[2*ks+1][3]);
    }

    // ---- O = P V  (V via ldmatrix.trans)
    float O[8][4];
    #pragma unroll
    for (int f = 0; f < 8; f++)
        #pragma unroll
        for (int e = 0; e < 4; e++) O[f][e] = 0.f;
    #pragma unroll
    for (int ks = 0; ks < 4; ks++) {
        #pragma unroll
        for (int nj = 0; nj < 4; nj++) {
            uint32_t r0, r1, r2, r3;
            ldsm4t(r0, r1, r2, r3,
                   sb + 16384u + swz((uint32_t)(16 * ks + lr) * 128 + (2 * nj + lc) * 16));
            mma16816(O[2*nj+0], aP[ks], r0, r1);
            mma16816(O[2*nj+1], aP[ks], r2, r3);
        }
    }

    // ---- store O -> g_actA (token-major bf16)
    const int r0row = 16 * wid + (lane >> 2);
    const int q2 = (lane & 3) * 2;
    #pragma unroll
    for (int f = 0; f < 8; f++) {
        __nv_bfloat16* d0 = g_actA + (size_t)(win * 64 + r0row) * C_ + head * 64 + 8 * f + q2;
        *(__nv_bfloat162*)d0 = __floats2bfloat162_rn(O[f][0], O[f][1]);
        *(__nv_bfloat162*)(d0 + 8 * C_) = __floats2bfloat162_rn(O[f][2], O[f][3]);
    }
}

// ---------------- launcher ----------------
extern "C" void kernel_launch(void* const* d_in, const int* in_sizes, int n_in,
                              void* d_out, int out_size) {
    const float* x_seq  = (const float*)d_in[0];
    const float* c_in   = (const float*)d_in[1];
    const float* qkv_w  = (const float*)d_in[2];
    const float* qkv_b  = (const float*)d_in[3];
    const float* proj_w = (const float*)d_in[4];
    const float* proj_b = (const float*)d_in[5];
    const float* fc1_w  = (const float*)d_in[6];
    const float* fc1_b  = (const float*)d_in[7];
    const float* fc2_w  = (const float*)d_in[8];
    const float* fc2_b  = (const float*)d_in[9];
    const float* ada_w  = (const float*)d_in[10];
    const float* ada_b  = (const float*)d_in[11];
    float* out = (float*)d_out;

    cudaFuncSetAttribute(gemm_tc<0>, cudaFuncAttributeMaxDynamicSharedMemorySize, GEMM_SMEM);
    cudaFuncSetAttribute(gemm_tc<1>, cudaFuncAttributeMaxDynamicSharedMemorySize, GEMM_SMEM);
    cudaFuncSetAttribute(gemm_tc<2>, cudaFuncAttributeMaxDynamicSharedMemorySize, GEMM_SMEM);
    cudaFuncSetAttribute(gemm_tc<3>, cudaFuncAttributeMaxDynamicSharedMemorySize, GEMM_SMEM);

    __nv_bfloat16 *wq, *wp, *w1, *w2;
    cudaGetSymbolAddress((void**)&wq, g_wqkv);
    cudaGetSymbolAddress((void**)&wp, g_wproj);
    cudaGetSymbolAddress((void**)&w1, g_wfc1);
    cudaGetSymbolAddress((void**)&w2, g_wfc2);

    f2bf_kernel<<<(3*C_*C_/4 + 255)/256, 256>>>(qkv_w,  wq, 3*C_*C_);
    f2bf_kernel<<<(C_*C_/4   + 255)/256, 256>>>(proj_w, wp, C_*C_);
    f2bf_kernel<<<(HID*C_/4  + 255)/256, 256>>>(fc1_w,  w1, HID*C_);
    f2bf_kernel<<<(C_*HID/4  + 255)/256, 256>>>(fc2_w,  w2, C_*HID);

    silu_kernel<<<(NB*C_ + 255)/256, 256>>>(c_in);
    ada_kernel<<<dim3(ADA6/4, NB), 128>>>(ada_w, ada_b);

    ln_mod_kernel<0><<<M_TOT, 256>>>(x_seq);
    gemm_tc<0><<<dim3(18, 256), 256, GEMM_SMEM>>>(qkv_b, nullptr, nullptr);
    attn_hmma<<<512*NHEAD, 128>>>();
    gemm_tc<1><<<dim3(6, 256), 256, GEMM_SMEM>>>(proj_b, x_seq, nullptr);
    ln_mod_kernel<1><<<M_TOT, 256>>>(nullptr);
    gemm_tc<2><<<dim3(24, 256), 256, GEMM_SMEM>>>(fc1_b, nullptr, nullptr);
    gemm_tc<3><<<dim3(6, 256), 256, GEMM_SMEM>>>(fc2_b, nullptr, out);
}

// round 5
// speedup vs baseline: 3.6877x; 1.0014x over previous
#include <cuda_runtime.h>
#include <cuda_bf16.h>
#include <cstdint>

// ---------------- problem constants ----------------
#define NB     8
#define C_     768
#define NHEAD  12
#define M_TOT  32768
#define HID    3072
#define ADA6   (6*C_)
#define REGSZ  ((size_t)M_TOT * C_)
#define KC     64

// ---------------- scratch (device globals) ----------------
__device__ float g_silu[NB*C_];
__device__ float g_ada[NB*ADA6];
__device__ __nv_bfloat16 g_qkv[(size_t)3*M_TOT*C_];
__device__ float g_xnew[(size_t)M_TOT*C_];
__device__ __nv_bfloat16 g_actA[(size_t)M_TOT*C_];
__device__ __nv_bfloat16 g_actB[(size_t)M_TOT*HID];
__device__ __nv_bfloat16 g_wqkv[3*C_*C_];
__device__ __nv_bfloat16 g_wproj[C_*C_];
__device__ __nv_bfloat16 g_wfc1[HID*C_];
__device__ __nv_bfloat16 g_wfc2[C_*HID];

// ---------------- ptx helpers ----------------
__device__ __forceinline__ uint32_t smem_u32(const void* p) {
    uint32_t a;
    asm("{ .reg .u64 t; cvta.to.shared.u64 t, %1; cvt.u32.u64 %0, t; }" : "=r"(a) : "l"(p));
    return a;
}
__device__ __forceinline__ void cp16(uint32_t dst, const void* src) {
    asm volatile("cp.async.cg.shared.global [%0], [%1], 16;" :: "r"(dst), "l"(src));
}
__device__ __forceinline__ void cp_commit() { asm volatile("cp.async.commit_group;" ::: "memory"); }
template<int N> __device__ __forceinline__ void cp_wait() {
    asm volatile("cp.async.wait_group %0;" :: "n"(N) : "memory");
}
__device__ __forceinline__ void ldsm4(uint32_t& r0, uint32_t& r1, uint32_t& r2, uint32_t& r3,
                                      uint32_t addr) {
    asm volatile("ldmatrix.sync.aligned.m8n8.x4.shared.b16 {%0,%1,%2,%3}, [%4];"
                 : "=r"(r0), "=r"(r1), "=r"(r2), "=r"(r3) : "r"(addr));
}
__device__ __forceinline__ void ldsm4t(uint32_t& r0, uint32_t& r1, uint32_t& r2, uint32_t& r3,
                                       uint32_t addr) {
    asm volatile("ldmatrix.sync.aligned.m8n8.x4.trans.shared.b16 {%0,%1,%2,%3}, [%4];"
                 : "=r"(r0), "=r"(r1), "=r"(r2), "=r"(r3) : "r"(addr));
}
__device__ __forceinline__ void mma16816(float* c, const uint32_t* a,
                                         uint32_t b0, uint32_t b1) {
    asm volatile(
        "mma.sync.aligned.m16n8k16.row.col.f32.bf16.bf16.f32 "
        "{%0,%1,%2,%3}, {%4,%5,%6,%7}, {%8,%9}, {%0,%1,%2,%3};"
        : "+f"(c[0]), "+f"(c[1]), "+f"(c[2]), "+f"(c[3])
        : "r"(a[0]), "r"(a[1]), "r"(a[2]), "r"(a[3]), "r"(b0), "r"(b1));
}
__device__ __forceinline__ uint32_t swz(uint32_t o) { return o ^ ((o >> 3) & 0x70); }
__device__ __forceinline__ uint32_t packbf(float x, float y) {
    __nv_bfloat162 h = __floats2bfloat162_rn(x, y);
    return *(uint32_t*)&h;
}
__device__ __forceinline__ float tanha(float x) {
    float y;
    asm("tanh.approx.f32 %0, %1;" : "=f"(y) : "f"(x));
    return y;
}

// ---------------- tiny kernels ----------------
__global__ void silu_kernel(const float* __restrict__ c) {
    int i = blockIdx.x * blockDim.x + threadIdx.x;
    if (i < NB*C_) {
        float v = c[i];
        g_silu[i] = v / (1.f + expf(-v));
    }
}

__global__ void ada_kernel(const float* __restrict__ ada_w,
                           const float* __restrict__ ada_b) {
    const int warp = threadIdx.x >> 5, lane = threadIdx.x & 31;
    const int j = blockIdx.x * 4 + warp;
    const int n = blockIdx.y;
    const float* wrow = ada_w + (size_t)j * C_;
    const float* crow = g_silu + n * C_;
    float s = 0.f;
    for (int k = lane; k < C_; k += 32) s += crow[k] * wrow[k];
    #pragma unroll
    for (int o = 16; o > 0; o >>= 1) s += __shfl_xor_sync(0xffffffffu, s, o);
    if (lane == 0) g_ada[n*ADA6 + j] = s + ada_b[j];
}

__global__ void f2bf_kernel(const float* __restrict__ s, __nv_bfloat16* __restrict__ d, int n) {
    int i = (blockIdx.x * blockDim.x + threadIdx.x) * 4;
    if (i < n) {
        float4 v = *(const float4*)(s + i);
        ((__nv_bfloat162*)(d + i))[0] = __floats2bfloat162_rn(v.x, v.y);
        ((__nv_bfloat162*)(d + i))[1] = __floats2bfloat162_rn(v.z, v.w);
    }
}

// LayerNorm + adaLN modulation -> bf16 into g_actA
template<int SEQ>
__global__ void ln_mod_kernel(const float* __restrict__ xin) {
    const int t = blockIdx.x;
    const int tid = threadIdx.x;
    int n;
    const float* xr;
    if (SEQ) {
        n = t >> 12;
        xr = g_xnew + (size_t)t * C_;
    } else {
        const int win = t >> 6, tw = t & 63;
        n = win >> 6;
        const int wi = win & 63;
        const int gi = ((wi >> 3) << 3) + (tw >> 3);
        const int gj = ((wi & 7) << 3) + (tw & 7);
        const int i0 = (gi + 4) & 63, j0 = (gj + 4) & 63;
        xr = xin + (((size_t)n << 12) + (i0 << 6) + j0) * C_;
    }
    float v0 = xr[tid], v1 = xr[tid + 256], v2 = xr[tid + 512];
    float s  = v0 + v1 + v2;
    float ss = v0*v0 + v1*v1 + v2*v2;
    __shared__ float red[18];
    #pragma unroll
    for (int o = 16; o > 0; o >>= 1) {
        s  += __shfl_xor_sync(0xffffffffu, s,  o);
        ss += __shfl_xor_sync(0xffffffffu, ss, o);
    }
    if ((tid & 31) == 0) { red[tid >> 5] = s; red[8 + (tid >> 5)] = ss; }
    __syncthreads();
    if (tid == 0) {
        float a = 0.f, b = 0.f;
        #pragma unroll
        for (int w = 0; w < 8; w++) { a += red[w]; b += red[8 + w]; }
        const float mean = a * (1.f / 768.f);
        const float var  = b * (1.f / 768.f) - mean * mean;
        red[16] = mean;
        red[17] = rsqrtf(var + 1e-6f);
    }
    __syncthreads();
    const float mean = red[16], rstd = red[17];
    const float* scp = g_ada + n*ADA6 + (SEQ ? 4 : 1) * C_;
    const float* shp = g_ada + n*ADA6 + (SEQ ? 3 : 0) * C_;
    __nv_bfloat16* outr = g_actA + (size_t)t * C_;
    float vv[3] = {v0, v1, v2};
    #pragma unroll
    for (int e = 0; e < 3; e++) {
        const int cix = tid + e * 256;
        const float hn = (vv[e] - mean) * rstd;
        outr[cix] = __float2bfloat16(hn * (1.f + scp[cix]) + shp[cix]);
    }
}

// ---------------- HMMA bf16 GEMM: C[m,n] = sum_k A[m,k]*W[n,k] ----------------
// CTA 128x256, 8 warps (2x4), warp tile 64x64. K chunks of 64, 3-buffer ring.
#define BM 128
#define BN 256
#define BUFB ((BM + BN) * 128)       // 49152 bytes per buffer
#define GEMM_SMEM (3 * BUFB)         // 147456

template<int MODE>
__global__ void __launch_bounds__(256, 1) gemm_tc(
    const float* __restrict__ bias,
    const float* __restrict__ x_seq,
    float* __restrict__ dout)
{
    constexpr int K   = (MODE == 3) ? HID : C_;
    constexpr int NCH = K / KC;
    const __nv_bfloat16* A = (MODE == 3) ? g_actB : g_actA;
    const __nv_bfloat16* W = (MODE == 0) ? g_wqkv : (MODE == 1) ? g_wproj
                           : (MODE == 2) ? g_wfc1 : g_wfc2;

    extern __shared__ char smem[];
    const uint32_t s0 = smem_u32(smem);
    const int tid = threadIdx.x;
    const int wid = tid >> 5, lane = tid & 31;
    const int bm = blockIdx.y * BM, bn = blockIdx.x * BN;

    // producer: every thread loads W row (bn+tid); threads <128 also load A row (bm+tid)
    const __nv_bfloat16* Brow = W + (size_t)(bn + tid) * K;
    const __nv_bfloat16* Arow = A + (size_t)(bm + (tid & 127)) * K;
    uint32_t bofs[8], aofs[8];
    #pragma unroll
    for (int s = 0; s < 8; s++) {
        uint32_t o = (uint32_t)tid * 128 + s * 16;
        bofs[s] = 16384u + swz(o);
        uint32_t oa = (uint32_t)(tid & 127) * 128 + s * 16;
        aofs[s] = swz(oa);
    }
    auto load_chunk = [&](int i) {
        const uint32_t buf = s0 + (uint32_t)(i % 3) * BUFB;
        const __nv_bfloat16* bsrc = Brow + i * KC;
        #pragma unroll
        for (int s = 0; s < 8; s++) cp16(buf + bofs[s], bsrc + s * 8);
        if (tid < 128) {
            const __nv_bfloat16* asrc = Arow + i * KC;
            #pragma unroll
            for (int s = 0; s < 8; s++) cp16(buf + aofs[s], asrc + s * 8);
        }
        cp_commit();
    };
    load_chunk(0); load_chunk(1);

    // consumer: warp (wm, wn) owns rows wm*64.., cols wn*64..
    const int wm = wid >> 2, wn = wid & 3;
    uint32_t aOff[4], aXor[4];
    #pragma unroll
    for (int mi = 0; mi < 4; mi++) {
        const int r = wm * 64 + mi * 16 + (lane & 15);
        aOff[mi] = (uint32_t)r * 128 + ((lane >> 4) << 4);
        aXor[mi] = ((uint32_t)(r & 7)) << 4;
    }
    uint32_t bOff[4], bXor[4];
    #pragma unroll
    for (int nj = 0; nj < 4; nj++) {
        const int r = wn * 64 + nj * 16 + (lane & 15);
        bOff[nj] = 16384u + (uint32_t)r * 128 + ((lane >> 4) << 4);
        bXor[nj] = ((uint32_t)(r & 7)) << 4;
    }

    float acc[4][8][4];
    #pragma unroll
    for (int mi = 0; mi < 4; mi++)
        #pragma unroll
        for (int ni = 0; ni < 8; ni++)
            #pragma unroll
            for (int e = 0; e < 4; e++) acc[mi][ni][e] = 0.f;

    for (int i = 0; i < NCH; i++) {
        if (i < NCH - 1) cp_wait<1>(); else cp_wait<0>();
        __syncthreads();
        if (i + 2 < NCH) load_chunk(i + 2);
        const uint32_t buf = s0 + (uint32_t)(i % 3) * BUFB;
        #pragma unroll
        for (int ks = 0; ks < 4; ks++) {
            const uint32_t kb = (uint32_t)ks * 32;
            uint32_t a_[4][4];
            #pragma unroll
            for (int mi = 0; mi < 4; mi++)
                ldsm4(a_[mi][0], a_[mi][1], a_[mi][2], a_[mi][3],
                      buf + (aOff[mi] & ~0x70u) + (((aOff[mi] & 0x70u) + kb) ^ aXor[mi]));
            uint32_t b_[4][4];
            #pragma unroll
            for (int nj = 0; nj < 4; nj++)
                ldsm4(b_[nj][0], b_[nj][1], b_[nj][2], b_[nj][3],
                      buf + (bOff[nj] & ~0x70u) + (((bOff[nj] & 0x70u) + kb) ^ bXor[nj]));
            #pragma unroll
            for (int mi = 0; mi < 4; mi++) {
                #pragma unroll
                for (int nj = 0; nj < 4; nj++) {
                    mma16816(acc[mi][nj*2+0], a_[mi], b_[nj][0], b_[nj][2]);
                    mma16816(acc[mi][nj*2+1], a_[mi], b_[nj][1], b_[nj][3]);
                }
            }
        }
    }

    // ---------------- epilogue ----------------
    const int rIn = lane >> 2;
    const int cIn = (lane & 3) * 2;
    #pragma unroll
    for (int mi = 0; mi < 4; mi++) {
        #pragma unroll
        for (int h = 0; h < 2; h++) {
            const int row = bm + wm * 64 + mi * 16 + rIn + h * 8;
            if constexpr (MODE == 0) {
                const int win = row >> 6, tw = row & 63;
                #pragma unroll
                for (int ni = 0; ni < 8; ni++) {
                    const int g = bn + wn * 64 + ni * 8 + cIn;
                    const int which = g / 768;
                    const int head = (g >> 6) % 12;
                    const int d0 = g & 63;
                    __nv_bfloat16* dst = g_qkv + (size_t)which * REGSZ
                               + (((size_t)(win * NHEAD + head)) << 12) + (tw << 6) + d0;
                    *(__nv_bfloat162*)dst = __floats2bfloat162_rn(
                        acc[mi][ni][h*2+0] + __ldg(bias + g),
                        acc[mi][ni][h*2+1] + __ldg(bias + g + 1));
                }
            } else if constexpr (MODE == 1) {
                const int win = row >> 6, tw = row & 63;
                const int n = win >> 6, wi = win & 63;
                const int gi = ((wi >> 3) << 3) + (tw >> 3);
                const int gj = ((wi & 7) << 3) + (tw & 7);
                const int i0 = (gi + 4) & 63, j0 = (gj + 4) & 63;
                const size_t srow = ((size_t)n << 12) + (i0 << 6) + j0;
                const float* xr = x_seq + srow * C_;
                float* dst = g_xnew + srow * C_;
                const float* gp = g_ada + n * ADA6 + 2 * C_;
                #pragma unroll
                for (int ni = 0; ni < 8; ni++) {
                    const int g = bn + wn * 64 + ni * 8 + cIn;
                    float2 v;
                    v.x = xr[g]   + gp[g]   * (acc[mi][ni][h*2+0] + __ldg(bias + g));
                    v.y = xr[g+1] + gp[g+1] * (acc[mi][ni][h*2+1] + __ldg(bias + g + 1));
                    *(float2*)(dst + g) = v;
                }
            } else if constexpr (MODE == 2) {
                __nv_bfloat16* dst = g_actB + (size_t)row * HID;
                #pragma unroll
                for (int ni = 0; ni < 8; ni++) {
                    const int g = bn + wn * 64 + ni * 8 + cIn;
                    float u0 = acc[mi][ni][h*2+0] + __ldg(bias + g);
                    float u1 = acc[mi][ni][h*2+1] + __ldg(bias + g + 1);
                    float t0 = tanha(0.7978845608028654f * (u0 + 0.044715f * u0 * u0 * u0));
                    float t1 = tanha(0.7978845608028654f * (u1 + 0.044715f * u1 * u1 * u1));
                    *(__nv_bfloat162*)(dst + g) =
                        __floats2bfloat162_rn(0.5f * u0 * (1.f + t0), 0.5f * u1 * (1.f + t1));
                }
            } else {
                const int n = row >> 12;
                const float* xr = g_xnew + (size_t)row * C_;
                const float* gp = g_ada + n * ADA6 + 5 * C_;
                float* dst = dout + (size_t)row * C_;
                #pragma unroll
                for (int ni = 0; ni < 8; ni++) {
                    const int g = bn + wn * 64 + ni * 8 + cIn;
                    float2 v;
                    v.x = xr[g]   + gp[g]   * (acc[mi][ni][h*2+0] + __ldg(bias + g));
                    v.y = xr[g+1] + gp[g+1] * (acc[mi][ni][h*2+1] + __ldg(bias + g + 1));
                    *(float2*)(dst + g) = v;
                }
            }
        }
    }
}

// ---------------- HMMA window attention: one block per (window, head) ----------------
__global__ void __launch_bounds__(128) attn_hmma() {
    __shared__ __align__(1024) __nv_bfloat16 sm[3 * 4096];   // q | k | v
    const uint32_t sb = smem_u32(sm);
    const int bid = blockIdx.x;
    const int win = bid / 12, head = bid - 12 * win;
    const int tid = threadIdx.x, wid = tid >> 5, lane = tid & 31;
    const __nv_bfloat16* qb = g_qkv + (size_t)bid * 4096;
    const __nv_bfloat16* kb = qb + REGSZ;
    const __nv_bfloat16* vb = qb + 2 * REGSZ;

    {
        const int r = tid & 63;
        const __nv_bfloat16* src = ((tid < 64) ? qb : kb) + r * 64;
        const uint32_t base = sb + ((tid < 64) ? 0u : 8192u);
        #pragma unroll
        for (int s = 0; s < 8; s++)
            cp16(base + swz((uint32_t)r * 128 + s * 16), src + s * 8);
        const int vr = tid >> 1;
        const int c0 = (tid & 1) * 4;
        #pragma unroll
        for (int s = 0; s < 4; s++)
            cp16(sb + 16384u + swz((uint32_t)vr * 128 + (c0 + s) * 16), vb + vr * 64 + (c0 + s) * 8);
    }
    cp_commit();
    cp_wait<0>();
    __syncthreads();

    const int lr = lane & 15, lc = lane >> 4;

    uint32_t aF[4][4];
    #pragma unroll
    for (int ks = 0; ks < 4; ks++)
        ldsm4(aF[ks][0], aF[ks][1], aF[ks][2], aF[ks][3],
              sb + swz((uint32_t)(16 * wid + lr) * 128 + lc * 16 + ks * 32));

    float S[8][4];
    #pragma unroll
    for (int f = 0; f < 8; f++)
        #pragma unroll
        for (int e = 0; e < 4; e++) S[f][e] = 0.f;

    #pragma unroll
    for (int nj = 0; nj < 4; nj++) {
        #pragma unroll
        for (int ks = 0; ks < 4; ks++) {
            uint32_t b0, b1, b2, b3;
            ldsm4(b0, b1, b2, b3,
                  sb + 8192u + swz((uint32_t)(nj * 16 + lr) * 128 + lc * 16 + ks * 32));
            mma16816(S[2*nj+0], aF[ks], b0, b2);
            mma16816(S[2*nj+1], aF[ks], b1, b3);
        }
    }

    float mx0 = -1e30f, mx1 = -1e30f;
    #pragma unroll
    for (int f = 0; f < 8; f++) {
        #pragma unroll
        for (int e = 0; e < 4; e++) S[f][e] *= 0.125f;
        mx0 = fmaxf(mx0, fmaxf(S[f][0], S[f][1]));
        mx1 = fmaxf(mx1, fmaxf(S[f][2], S[f][3]));
    }
    mx0 = fmaxf(mx0, __shfl_xor_sync(0xffffffffu, mx0, 1));
    mx0 = fmaxf(mx0, __shfl_xor_sync(0xffffffffu, mx0, 2));
    mx1 = fmaxf(mx1, __shfl_xor_sync(0xffffffffu, mx1, 1));
    mx1 = fmaxf(mx1, __shfl_xor_sync(0xffffffffu, mx1, 2));
    float sm0 = 0.f, sm1 = 0.f;
    #pragma unroll
    for (int f = 0; f < 8; f++) {
        S[f][0] = __expf(S[f][0] - mx0); sm0 += S[f][0];
        S[f][1] = __expf(S[f][1] - mx0); sm0 += S[f][1];
        S[f][2] = __expf(S[f][2] - mx1); sm1 += S[f][2];
        S[f][3] = __expf(S[f][3] - mx1); sm1 += S[f][3];
    }
    sm0 += __shfl_xor_sync(0xffffffffu, sm0, 1);
    sm0 += __shfl_xor_sync(0xffffffffu, sm0, 2);
    sm1 += __shfl_xor_sync(0xffffffffu, sm1, 1);
    sm1 += __shfl_xor_sync(0xffffffffu, sm1, 2);
    const float iv0 = 1.f / sm0, iv1 = 1.f / sm1;
    #pragma unroll
    for (int f = 0; f < 8; f++) {
        S[f][0] *= iv0; S[f][1] *= iv0; S[f][2] *= iv1; S[f][3] *= iv1;
    }

    uint32_t aP[4][4];
    #pragma unroll
    for (int ks = 0; ks < 4; ks++) {
        aP[ks][0] = packbf(S[2*ks+0][0], S[2*ks+0][1]);
        aP[ks][1] = packbf(S[2*ks+0][2], S[2*ks+0][3]);
        aP[ks][2] = packbf(S[2*ks+1][0], S[2*ks+1][1]);
        aP[ks][3] = packbf(S[2*ks+1][2], S[2*ks+1][3]);
    }

    float O[8][4];
    #pragma unroll
    for (int f = 0; f < 8; f++)
        #pragma unroll
        for (int e = 0; e < 4; e++) O[f][e] = 0.f;
    #pragma unroll
    for (int ks = 0; ks < 4; ks++) {
        #pragma unroll
        for (int nj = 0; nj < 4; nj++) {
            uint32_t r0, r1, r2, r3;
            ldsm4t(r0, r1, r2, r3,
                   sb + 16384u + swz((uint32_t)(16 * ks + lr) * 128 + (2 * nj + lc) * 16));
            mma16816(O[2*nj+0], aP[ks], r0, r1);
            mma16816(O[2*nj+1], aP[ks], r2, r3);
        }
    }

    const int r0row = 16 * wid + (lane >> 2);
    const int q2 = (lane & 3) * 2;
    #pragma unroll
    for (int f = 0; f < 8; f++) {
        __nv_bfloat16* d0 = g_actA + (size_t)(win * 64 + r0row) * C_ + head * 64 + 8 * f + q2;
        *(__nv_bfloat162*)d0 = __floats2bfloat162_rn(O[f][0], O[f][1]);
        *(__nv_bfloat162*)(d0 + 8 * C_) = __floats2bfloat162_rn(O[f][2], O[f][3]);
    }
}

// ---------------- launcher ----------------
extern "C" void kernel_launch(void* const* d_in, const int* in_sizes, int n_in,
                              void* d_out, int out_size) {
    const float* x_seq  = (const float*)d_in[0];
    const float* c_in   = (const float*)d_in[1];
    const float* qkv_w  = (const float*)d_in[2];
    const float* qkv_b  = (const float*)d_in[3];
    const float* proj_w = (const float*)d_in[4];
    const float* proj_b = (const float*)d_in[5];
    const float* fc1_w  = (const float*)d_in[6];
    const float* fc1_b  = (const float*)d_in[7];
    const float* fc2_w  = (const float*)d_in[8];
    const float* fc2_b  = (const float*)d_in[9];
    const float* ada_w  = (const float*)d_in[10];
    const float* ada_b  = (const float*)d_in[11];
    float* out = (float*)d_out;

    cudaFuncSetAttribute(gemm_tc<0>, cudaFuncAttributeMaxDynamicSharedMemorySize, GEMM_SMEM);
    cudaFuncSetAttribute(gemm_tc<1>, cudaFuncAttributeMaxDynamicSharedMemorySize, GEMM_SMEM);
    cudaFuncSetAttribute(gemm_tc<2>, cudaFuncAttributeMaxDynamicSharedMemorySize, GEMM_SMEM);
    cudaFuncSetAttribute(gemm_tc<3>, cudaFuncAttributeMaxDynamicSharedMemorySize, GEMM_SMEM);

    __nv_bfloat16 *wq, *wp, *w1, *w2;
    cudaGetSymbolAddress((void**)&wq, g_wqkv);
    cudaGetSymbolAddress((void**)&wp, g_wproj);
    cudaGetSymbolAddress((void**)&w1, g_wfc1);
    cudaGetSymbolAddress((void**)&w2, g_wfc2);

    f2bf_kernel<<<(3*C_*C_/4 + 255)/256, 256>>>(qkv_w,  wq, 3*C_*C_);
    f2bf_kernel<<<(C_*C_/4   + 255)/256, 256>>>(proj_w, wp, C_*C_);
    f2bf_kernel<<<(HID*C_/4  + 255)/256, 256>>>(fc1_w,  w1, HID*C_);
    f2bf_kernel<<<(C_*HID/4  + 255)/256, 256>>>(fc2_w,  w2, C_*HID);

    silu_kernel<<<(NB*C_ + 255)/256, 256>>>(c_in);
    ada_kernel<<<dim3(ADA6/4, NB), 128>>>(ada_w, ada_b);

    ln_mod_kernel<0><<<M_TOT, 256>>>(x_seq);
    gemm_tc<0><<<dim3(9, 256), 256, GEMM_SMEM>>>(qkv_b, nullptr, nullptr);
    attn_hmma<<<512*NHEAD, 128>>>();
    gemm_tc<1><<<dim3(3, 256), 256, GEMM_SMEM>>>(proj_b, x_seq, nullptr);
    ln_mod_kernel<1><<<M_TOT, 256>>>(nullptr);
    gemm_tc<2><<<dim3(12, 256), 256, GEMM_SMEM>>>(fc1_b, nullptr, nullptr);
    gemm_tc<3><<<dim3(3, 256), 256, GEMM_SMEM>>>(fc2_b, nullptr, out);
}

// round 6
// speedup vs baseline: 3.7224x; 1.0094x over previous
#include <cuda_runtime.h>
#include <cuda_bf16.h>
#include <cstdint>

// ---------------- problem constants ----------------
#define NB     8
#define C_     768
#define NHEAD  12
#define M_TOT  32768
#define HID    3072
#define ADA6   (6*C_)
#define REGSZ  ((size_t)M_TOT * C_)
#define KC     64

// ---------------- scratch (device globals) ----------------
__device__ float g_silu[NB*C_];
__device__ float g_ada[NB*ADA6];
__device__ __nv_bfloat16 g_qkv[(size_t)3*M_TOT*C_];
__device__ float g_xnew[(size_t)M_TOT*C_];
__device__ __nv_bfloat16 g_actA[(size_t)M_TOT*C_];
__device__ __nv_bfloat16 g_actB[(size_t)M_TOT*HID];
__device__ __nv_bfloat16 g_wqkv[3*C_*C_];
__device__ __nv_bfloat16 g_wproj[C_*C_];
__device__ __nv_bfloat16 g_wfc1[HID*C_];
__device__ __nv_bfloat16 g_wfc2[C_*HID];

// ---------------- ptx helpers ----------------
__device__ __forceinline__ uint32_t smem_u32(const void* p) {
    uint32_t a;
    asm("{ .reg .u64 t; cvta.to.shared.u64 t, %1; cvt.u32.u64 %0, t; }" : "=r"(a) : "l"(p));
    return a;
}
__device__ __forceinline__ void cp16(uint32_t dst, const void* src) {
    asm volatile("cp.async.cg.shared.global [%0], [%1], 16;" :: "r"(dst), "l"(src));
}
__device__ __forceinline__ void cp_commit() { asm volatile("cp.async.commit_group;" ::: "memory"); }
template<int N> __device__ __forceinline__ void cp_wait() {
    asm volatile("cp.async.wait_group %0;" :: "n"(N) : "memory");
}
__device__ __forceinline__ void ldsm4(uint32_t& r0, uint32_t& r1, uint32_t& r2, uint32_t& r3,
                                      uint32_t addr) {
    asm volatile("ldmatrix.sync.aligned.m8n8.x4.shared.b16 {%0,%1,%2,%3}, [%4];"
                 : "=r"(r0), "=r"(r1), "=r"(r2), "=r"(r3) : "r"(addr));
}
__device__ __forceinline__ void ldsm4t(uint32_t& r0, uint32_t& r1, uint32_t& r2, uint32_t& r3,
                                       uint32_t addr) {
    asm volatile("ldmatrix.sync.aligned.m8n8.x4.trans.shared.b16 {%0,%1,%2,%3}, [%4];"
                 : "=r"(r0), "=r"(r1), "=r"(r2), "=r"(r3) : "r"(addr));
}
__device__ __forceinline__ void mma16816(float* c, const uint32_t* a,
                                         uint32_t b0, uint32_t b1) {
    asm volatile(
        "mma.sync.aligned.m16n8k16.row.col.f32.bf16.bf16.f32 "
        "{%0,%1,%2,%3}, {%4,%5,%6,%7}, {%8,%9}, {%0,%1,%2,%3};"
        : "+f"(c[0]), "+f"(c[1]), "+f"(c[2]), "+f"(c[3])
        : "r"(a[0]), "r"(a[1]), "r"(a[2]), "r"(a[3]), "r"(b0), "r"(b1));
}
__device__ __forceinline__ uint32_t swz(uint32_t o) { return o ^ ((o >> 3) & 0x70); }
__device__ __forceinline__ uint32_t packbf(float x, float y) {
    __nv_bfloat162 h = __floats2bfloat162_rn(x, y);
    return *(uint32_t*)&h;
}
__device__ __forceinline__ float tanha(float x) {
    float y;
    asm("tanh.approx.f32 %0, %1;" : "=f"(y) : "f"(x));
    return y;
}

// ---------------- tiny kernels ----------------
__global__ void silu_kernel(const float* __restrict__ c) {
    int i = blockIdx.x * blockDim.x + threadIdx.x;
    if (i < NB*C_) {
        float v = c[i];
        g_silu[i] = v / (1.f + expf(-v));
    }
}

__global__ void ada_kernel(const float* __restrict__ ada_w,
                           const float* __restrict__ ada_b) {
    const int warp = threadIdx.x >> 5, lane = threadIdx.x & 31;
    const int j = blockIdx.x * 4 + warp;
    const int n = blockIdx.y;
    const float* wrow = ada_w + (size_t)j * C_;
    const float* crow = g_silu + n * C_;
    float s = 0.f;
    for (int k = lane; k < C_; k += 32) s += crow[k] * wrow[k];
    #pragma unroll
    for (int o = 16; o > 0; o >>= 1) s += __shfl_xor_sync(0xffffffffu, s, o);
    if (lane == 0) g_ada[n*ADA6 + j] = s + ada_b[j];
}

__global__ void f2bf_kernel(const float* __restrict__ s, __nv_bfloat16* __restrict__ d, int n) {
    int i = (blockIdx.x * blockDim.x + threadIdx.x) * 4;
    if (i < n) {
        float4 v = *(const float4*)(s + i);
        ((__nv_bfloat162*)(d + i))[0] = __floats2bfloat162_rn(v.x, v.y);
        ((__nv_bfloat162*)(d + i))[1] = __floats2bfloat162_rn(v.z, v.w);
    }
}

// LayerNorm + adaLN modulation -> bf16 into g_actA
template<int SEQ>
__global__ void ln_mod_kernel(const float* __restrict__ xin) {
    const int t = blockIdx.x;
    const int tid = threadIdx.x;
    int n;
    const float* xr;
    if (SEQ) {
        n = t >> 12;
        xr = g_xnew + (size_t)t * C_;
    } else {
        const int win = t >> 6, tw = t & 63;
        n = win >> 6;
        const int wi = win & 63;
        const int gi = ((wi >> 3) << 3) + (tw >> 3);
        const int gj = ((wi & 7) << 3) + (tw & 7);
        const int i0 = (gi + 4) & 63, j0 = (gj + 4) & 63;
        xr = xin + (((size_t)n << 12) + (i0 << 6) + j0) * C_;
    }
    float v0 = xr[tid], v1 = xr[tid + 256], v2 = xr[tid + 512];
    float s  = v0 + v1 + v2;
    float ss = v0*v0 + v1*v1 + v2*v2;
    __shared__ float red[18];
    #pragma unroll
    for (int o = 16; o > 0; o >>= 1) {
        s  += __shfl_xor_sync(0xffffffffu, s,  o);
        ss += __shfl_xor_sync(0xffffffffu, ss, o);
    }
    if ((tid & 31) == 0) { red[tid >> 5] = s; red[8 + (tid >> 5)] = ss; }
    __syncthreads();
    if (tid == 0) {
        float a = 0.f, b = 0.f;
        #pragma unroll
        for (int w = 0; w < 8; w++) { a += red[w]; b += red[8 + w]; }
        const float mean = a * (1.f / 768.f);
        const float var  = b * (1.f / 768.f) - mean * mean;
        red[16] = mean;
        red[17] = rsqrtf(var + 1e-6f);
    }
    __syncthreads();
    const float mean = red[16], rstd = red[17];
    const float* scp = g_ada + n*ADA6 + (SEQ ? 4 : 1) * C_;
    const float* shp = g_ada + n*ADA6 + (SEQ ? 3 : 0) * C_;
    __nv_bfloat16* outr = g_actA + (size_t)t * C_;
    float vv[3] = {v0, v1, v2};
    #pragma unroll
    for (int e = 0; e < 3; e++) {
        const int cix = tid + e * 256;
        const float hn = (vv[e] - mean) * rstd;
        outr[cix] = __float2bfloat16(hn * (1.f + scp[cix]) + shp[cix]);
    }
}

// ---------------- HMMA bf16 GEMM: C[m,n] = sum_k A[m,k]*W[n,k] ----------------
// CTA 128x256, 8 warps (2x4), warp tile 64x64. 4-deep smem ring, reg-double-buffered
// LDSM, chunk-boundary sync hidden behind the last MMA burst.
#define BM 128
#define BN 256
#define BUFB ((BM + BN) * 128)       // 49152 bytes per buffer
#define GEMM_SMEM (4 * BUFB)         // 196608

template<int MODE>
__global__ void __launch_bounds__(256, 1) gemm_tc(
    const float* __restrict__ bias,
    const float* __restrict__ x_seq,
    float* __restrict__ dout)
{
    constexpr int K   = (MODE == 3) ? HID : C_;
    constexpr int NCH = K / KC;
    const __nv_bfloat16* A = (MODE == 3) ? g_actB : g_actA;
    const __nv_bfloat16* W = (MODE == 0) ? g_wqkv : (MODE == 1) ? g_wproj
                           : (MODE == 2) ? g_wfc1 : g_wfc2;

    extern __shared__ char smem[];
    const uint32_t s0 = smem_u32(smem);
    const int tid = threadIdx.x;
    const int wid = tid >> 5, lane = tid & 31;
    const int bm = blockIdx.y * BM, bn = blockIdx.x * BN;

    const __nv_bfloat16* Brow = W + (size_t)(bn + tid) * K;
    const __nv_bfloat16* Arow = A + (size_t)(bm + (tid & 127)) * K;
    uint32_t bofs[8], aofs[8];
    #pragma unroll
    for (int s = 0; s < 8; s++) {
        bofs[s] = 16384u + swz((uint32_t)tid * 128 + s * 16);
        aofs[s] = swz((uint32_t)(tid & 127) * 128 + s * 16);
    }
    auto load_chunk = [&](int i) {
        const uint32_t buf = s0 + (uint32_t)(i & 3) * BUFB;
        const __nv_bfloat16* bsrc = Brow + i * KC;
        #pragma unroll
        for (int s = 0; s < 8; s++) cp16(buf + bofs[s], bsrc + s * 8);
        if (tid < 128) {
            const __nv_bfloat16* asrc = Arow + i * KC;
            #pragma unroll
            for (int s = 0; s < 8; s++) cp16(buf + aofs[s], asrc + s * 8);
        }
        cp_commit();
    };
    load_chunk(0); load_chunk(1); load_chunk(2);

    const int wm = wid >> 2, wn = wid & 3;
    uint32_t aOff[4], aXor[4];
    #pragma unroll
    for (int mi = 0; mi < 4; mi++) {
        const int r = wm * 64 + mi * 16 + (lane & 15);
        aOff[mi] = (uint32_t)r * 128 + ((lane >> 4) << 4);
        aXor[mi] = ((uint32_t)(r & 7)) << 4;
    }
    uint32_t bOff[4], bXor[4];
    #pragma unroll
    for (int nj = 0; nj < 4; nj++) {
        const int r = wn * 64 + nj * 16 + (lane & 15);
        bOff[nj] = 16384u + (uint32_t)r * 128 + ((lane >> 4) << 4);
        bXor[nj] = ((uint32_t)(r & 7)) << 4;
    }

    uint32_t aR[2][4][4], bR[2][4][4];
    auto do_ldsm = [&](uint32_t buf, int ks, int p) {
        const uint32_t kb = (uint32_t)ks * 32;
        #pragma unroll
        for (int mi = 0; mi < 4; mi++)
            ldsm4(aR[p][mi][0], aR[p][mi][1], aR[p][mi][2], aR[p][mi][3],
                  buf + (aOff[mi] & ~0x70u) + (((aOff[mi] & 0x70u) + kb) ^ aXor[mi]));
        #pragma unroll
        for (int nj = 0; nj < 4; nj++)
            ldsm4(bR[p][nj][0], bR[p][nj][1], bR[p][nj][2], bR[p][nj][3],
                  buf + (bOff[nj] & ~0x70u) + (((bOff[nj] & 0x70u) + kb) ^ bXor[nj]));
    };

    float acc[4][8][4];
    #pragma unroll
    for (int mi = 0; mi < 4; mi++)
        #pragma unroll
        for (int ni = 0; ni < 8; ni++)
            #pragma unroll
            for (int e = 0; e < 4; e++) acc[mi][ni][e] = 0.f;

    cp_wait<2>();
    __syncthreads();
    do_ldsm(s0, 0, 0);

    for (int i = 0; i < NCH; i++) {
        const uint32_t buf = s0 + (uint32_t)(i & 3) * BUFB;
        #pragma unroll
        for (int ks = 0; ks < 4; ks++) {
            const int p = ks & 1;          // compile-time within unrolled body
            if (ks < 3) {
                do_ldsm(buf, ks + 1, p ^ 1);
            } else if (i + 1 < NCH) {
                if (i + 2 < NCH) cp_wait<1>(); else cp_wait<0>();
                __syncthreads();
                if (i + 3 < NCH) load_chunk(i + 3);
                do_ldsm(s0 + (uint32_t)((i + 1) & 3) * BUFB, 0, p ^ 1);
            }
            #pragma unroll
            for (int mi = 0; mi < 4; mi++) {
                #pragma unroll
                for (int nj = 0; nj < 4; nj++) {
                    mma16816(acc[mi][nj*2+0], aR[p][mi], bR[p][nj][0], bR[p][nj][2]);
                    mma16816(acc[mi][nj*2+1], aR[p][mi], bR[p][nj][1], bR[p][nj][3]);
                }
            }
        }
    }

    // ---------------- epilogue ----------------
    const int rIn = lane >> 2;
    const int cIn = (lane & 3) * 2;
    #pragma unroll
    for (int mi = 0; mi < 4; mi++) {
        #pragma unroll
        for (int h = 0; h < 2; h++) {
            const int row = bm + wm * 64 + mi * 16 + rIn + h * 8;
            if constexpr (MODE == 0) {
                const int win = row >> 6, tw = row & 63;
                #pragma unroll
                for (int ni = 0; ni < 8; ni++) {
                    const int g = bn + wn * 64 + ni * 8 + cIn;
                    const int which = g / 768;
                    const int head = (g >> 6) % 12;
                    const int d0 = g & 63;
                    __nv_bfloat16* dst = g_qkv + (size_t)which * REGSZ
                               + (((size_t)(win * NHEAD + head)) << 12) + (tw << 6) + d0;
                    *(__nv_bfloat162*)dst = __floats2bfloat162_rn(
                        acc[mi][ni][h*2+0] + __ldg(bias + g),
                        acc[mi][ni][h*2+1] + __ldg(bias + g + 1));
                }
            } else if constexpr (MODE == 1) {
                const int win = row >> 6, tw = row & 63;
                const int n = win >> 6, wi = win & 63;
                const int gi = ((wi >> 3) << 3) + (tw >> 3);
                const int gj = ((wi & 7) << 3) + (tw & 7);
                const int i0 = (gi + 4) & 63, j0 = (gj + 4) & 63;
                const size_t srow = ((size_t)n << 12) + (i0 << 6) + j0;
                const float* xr = x_seq + srow * C_;
                float* dst = g_xnew + srow * C_;
                const float* gp = g_ada + n * ADA6 + 2 * C_;
                #pragma unroll
                for (int ni = 0; ni < 8; ni++) {
                    const int g = bn + wn * 64 + ni * 8 + cIn;
                    float2 v;
                    v.x = xr[g]   + gp[g]   * (acc[mi][ni][h*2+0] + __ldg(bias + g));
                    v.y = xr[g+1] + gp[g+1] * (acc[mi][ni][h*2+1] + __ldg(bias + g + 1));
                    *(float2*)(dst + g) = v;
                }
            } else if constexpr (MODE == 2) {
                __nv_bfloat16* dst = g_actB + (size_t)row * HID;
                #pragma unroll
                for (int ni = 0; ni < 8; ni++) {
                    const int g = bn + wn * 64 + ni * 8 + cIn;
                    float u0 = acc[mi][ni][h*2+0] + __ldg(bias + g);
                    float u1 = acc[mi][ni][h*2+1] + __ldg(bias + g + 1);
                    float t0 = tanha(0.7978845608028654f * (u0 + 0.044715f * u0 * u0 * u0));
                    float t1 = tanha(0.7978845608028654f * (u1 + 0.044715f * u1 * u1 * u1));
                    *(__nv_bfloat162*)(dst + g) =
                        __floats2bfloat162_rn(0.5f * u0 * (1.f + t0), 0.5f * u1 * (1.f + t1));
                }
            } else {
                const int n = row >> 12;
                const float* xr = g_xnew + (size_t)row * C_;
                const float* gp = g_ada + n * ADA6 + 5 * C_;
                float* dst = dout + (size_t)row * C_;
                #pragma unroll
                for (int ni = 0; ni < 8; ni++) {
                    const int g = bn + wn * 64 + ni * 8 + cIn;
                    float2 v;
                    v.x = xr[g]   + gp[g]   * (acc[mi][ni][h*2+0] + __ldg(bias + g));
                    v.y = xr[g+1] + gp[g+1] * (acc[mi][ni][h*2+1] + __ldg(bias + g + 1));
                    *(float2*)(dst + g) = v;
                }
            }
        }
    }
}

// ---------------- HMMA window attention: one block per (window, head) ----------------
__global__ void __launch_bounds__(128) attn_hmma() {
    __shared__ __align__(1024) __nv_bfloat16 sm[3 * 4096];   // q | k | v
    const uint32_t sb = smem_u32(sm);
    const int bid = blockIdx.x;
    const int win = bid / 12, head = bid - 12 * win;
    const int tid = threadIdx.x, wid = tid >> 5, lane = tid & 31;
    const __nv_bfloat16* qb = g_qkv + (size_t)bid * 4096;
    const __nv_bfloat16* kb = qb + REGSZ;
    const __nv_bfloat16* vb = qb + 2 * REGSZ;

    {
        const int r = tid & 63;
        const __nv_bfloat16* src = ((tid < 64) ? qb : kb) + r * 64;
        const uint32_t base = sb + ((tid < 64) ? 0u : 8192u);
        #pragma unroll
        for (int s = 0; s < 8; s++)
            cp16(base + swz((uint32_t)r * 128 + s * 16), src + s * 8);
        const int vr = tid >> 1;
        const int c0 = (tid & 1) * 4;
        #pragma unroll
        for (int s = 0; s < 4; s++)
            cp16(sb + 16384u + swz((uint32_t)vr * 128 + (c0 + s) * 16), vb + vr * 64 + (c0 + s) * 8);
    }
    cp_commit();
    cp_wait<0>();
    __syncthreads();

    const int lr = lane & 15, lc = lane >> 4;

    uint32_t aF[4][4];
    #pragma unroll
    for (int ks = 0; ks < 4; ks++)
        ldsm4(aF[ks][0], aF[ks][1], aF[ks][2], aF[ks][3],
              sb + swz((uint32_t)(16 * wid + lr) * 128 + lc * 16 + ks * 32));

    float S[8][4];
    #pragma unroll
    for (int f = 0; f < 8; f++)
        #pragma unroll
        for (int e = 0; e < 4; e++) S[f][e] = 0.f;

    #pragma unroll
    for (int nj = 0; nj < 4; nj++) {
        #pragma unroll
        for (int ks = 0; ks < 4; ks++) {
            uint32_t b0, b1, b2, b3;
            ldsm4(b0, b1, b2, b3,
                  sb + 8192u + swz((uint32_t)(nj * 16 + lr) * 128 + lc * 16 + ks * 32));
            mma16816(S[2*nj+0], aF[ks], b0, b2);
            mma16816(S[2*nj+1], aF[ks], b1, b3);
        }
    }

    float mx0 = -1e30f, mx1 = -1e30f;
    #pragma unroll
    for (int f = 0; f < 8; f++) {
        #pragma unroll
        for (int e = 0; e < 4; e++) S[f][e] *= 0.125f;
        mx0 = fmaxf(mx0, fmaxf(S[f][0], S[f][1]));
        mx1 = fmaxf(mx1, fmaxf(S[f][2], S[f][3]));
    }
    mx0 = fmaxf(mx0, __shfl_xor_sync(0xffffffffu, mx0, 1));
    mx0 = fmaxf(mx0, __shfl_xor_sync(0xffffffffu, mx0, 2));
    mx1 = fmaxf(mx1, __shfl_xor_sync(0xffffffffu, mx1, 1));
    mx1 = fmaxf(mx1, __shfl_xor_sync(0xffffffffu, mx1, 2));
    float sm0 = 0.f, sm1 = 0.f;
    #pragma unroll
    for (int f = 0; f < 8; f++) {
        S[f][0] = __expf(S[f][0] - mx0); sm0 += S[f][0];
        S[f][1] = __expf(S[f][1] - mx0); sm0 += S[f][1];
        S[f][2] = __expf(S[f][2] - mx1); sm1 += S[f][2];
        S[f][3] = __expf(S[f][3] - mx1); sm1 += S[f][3];
    }
    sm0 += __shfl_xor_sync(0xffffffffu, sm0, 1);
    sm0 += __shfl_xor_sync(0xffffffffu, sm0, 2);
    sm1 += __shfl_xor_sync(0xffffffffu, sm1, 1);
    sm1 += __shfl_xor_sync(0xffffffffu, sm1, 2);
    const float iv0 = 1.f / sm0, iv1 = 1.f / sm1;
    #pragma unroll
    for (int f = 0; f < 8; f++) {
        S[f][0] *= iv0; S[f][1] *= iv0; S[f][2] *= iv1; S[f][3] *= iv1;
    }

    uint32_t aP[4][4];
    #pragma unroll
    for (int ks = 0; ks < 4; ks++) {
        aP[ks][0] = packbf(S[2*ks+0][0], S[2*ks+0][1]);
        aP[ks][1] = packbf(S[2*ks+0][2], S[2*ks+0][3]);
        aP[ks][2] = packbf(S[2*ks+1][0], S[2*ks+1][1]);
        aP[ks][3] = packbf(S[2*ks+1][2], S[2*ks+1][3]);
    }

    float O[8][4];
    #pragma unroll
    for (int f = 0; f < 8; f++)
        #pragma unroll
        for (int e = 0; e < 4; e++) O[f][e] = 0.f;
    #pragma unroll
    for (int ks = 0; ks < 4; ks++) {
        #pragma unroll
        for (int nj = 0; nj < 4; nj++) {
            uint32_t r0, r1, r2, r3;
            ldsm4t(r0, r1, r2, r3,
                   sb + 16384u + swz((uint32_t)(16 * ks + lr) * 128 + (2 * nj + lc) * 16));
            mma16816(O[2*nj+0], aP[ks], r0, r1);
            mma16816(O[2*nj+1], aP[ks], r2, r3);
        }
    }

    const int r0row = 16 * wid + (lane >> 2);
    const int q2 = (lane & 3) * 2;
    #pragma unroll
    for (int f = 0; f < 8; f++) {
        __nv_bfloat16* d0 = g_actA + (size_t)(win * 64 + r0row) * C_ + head * 64 + 8 * f + q2;
        *(__nv_bfloat162*)d0 = __floats2bfloat162_rn(O[f][0], O[f][1]);
        *(__nv_bfloat162*)(d0 + 8 * C_) = __floats2bfloat162_rn(O[f][2], O[f][3]);
    }
}

// ---------------- launcher ----------------
extern "C" void kernel_launch(void* const* d_in, const int* in_sizes, int n_in,
                              void* d_out, int out_size) {
    const float* x_seq  = (const float*)d_in[0];
    const float* c_in   = (const float*)d_in[1];
    const float* qkv_w  = (const float*)d_in[2];
    const float* qkv_b  = (const float*)d_in[3];
    const float* proj_w = (const float*)d_in[4];
    const float* proj_b = (const float*)d_in[5];
    const float* fc1_w  = (const float*)d_in[6];
    const float* fc1_b  = (const float*)d_in[7];
    const float* fc2_w  = (const float*)d_in[8];
    const float* fc2_b  = (const float*)d_in[9];
    const float* ada_w  = (const float*)d_in[10];
    const float* ada_b  = (const float*)d_in[11];
    float* out = (float*)d_out;

    cudaFuncSetAttribute(gemm_tc<0>, cudaFuncAttributeMaxDynamicSharedMemorySize, GEMM_SMEM);
    cudaFuncSetAttribute(gemm_tc<1>, cudaFuncAttributeMaxDynamicSharedMemorySize, GEMM_SMEM);
    cudaFuncSetAttribute(gemm_tc<2>, cudaFuncAttributeMaxDynamicSharedMemorySize, GEMM_SMEM);
    cudaFuncSetAttribute(gemm_tc<3>, cudaFuncAttributeMaxDynamicSharedMemorySize, GEMM_SMEM);

    __nv_bfloat16 *wq, *wp, *w1, *w2;
    cudaGetSymbolAddress((void**)&wq, g_wqkv);
    cudaGetSymbolAddress((void**)&wp, g_wproj);
    cudaGetSymbolAddress((void**)&w1, g_wfc1);
    cudaGetSymbolAddress((void**)&w2, g_wfc2);

    f2bf_kernel<<<(3*C_*C_/4 + 255)/256, 256>>>(qkv_w,  wq, 3*C_*C_);
    f2bf_kernel<<<(C_*C_/4   + 255)/256, 256>>>(proj_w, wp, C_*C_);
    f2bf_kernel<<<(HID*C_/4  + 255)/256, 256>>>(fc1_w,  w1, HID*C_);
    f2bf_kernel<<<(C_*HID/4  + 255)/256, 256>>>(fc2_w,  w2, C_*HID);

    silu_kernel<<<(NB*C_ + 255)/256, 256>>>(c_in);
    ada_kernel<<<dim3(ADA6/4, NB), 128>>>(ada_w, ada_b);

    ln_mod_kernel<0><<<M_TOT, 256>>>(x_seq);
    gemm_tc<0><<<dim3(9, 256), 256, GEMM_SMEM>>>(qkv_b, nullptr, nullptr);
    attn_hmma<<<512*NHEAD, 128>>>();
    gemm_tc<1><<<dim3(3, 256), 256, GEMM_SMEM>>>(proj_b, x_seq, nullptr);
    ln_mod_kernel<1><<<M_TOT, 256>>>(nullptr);
    gemm_tc<2><<<dim3(12, 256), 256, GEMM_SMEM>>>(fc1_b, nullptr, nullptr);
    gemm_tc<3><<<dim3(3, 256), 256, GEMM_SMEM>>>(fc2_b, nullptr, out);
}

// round 7
// speedup vs baseline: 3.7336x; 1.0030x over previous
#include <cuda_runtime.h>
#include <cuda_bf16.h>
#include <cstdint>

// ---------------- problem constants ----------------
#define NB     8
#define C_     768
#define NHEAD  12
#define M_TOT  32768
#define HID    3072
#define ADA6   (6*C_)
#define REGSZ  ((size_t)M_TOT * C_)
#define KC     64

// ---------------- scratch (device globals) ----------------
__device__ float g_ada[NB*ADA6];
__device__ __nv_bfloat16 g_qkv[(size_t)3*M_TOT*C_];
__device__ float g_xnew[(size_t)M_TOT*C_];
__device__ __nv_bfloat16 g_actA[(size_t)M_TOT*C_];
__device__ __nv_bfloat16 g_actB[(size_t)M_TOT*HID];
__device__ __nv_bfloat16 g_wqkv[3*C_*C_];
__device__ __nv_bfloat16 g_wproj[C_*C_];
__device__ __nv_bfloat16 g_wfc1[HID*C_];
__device__ __nv_bfloat16 g_wfc2[C_*HID];

// ---------------- ptx helpers ----------------
__device__ __forceinline__ uint32_t smem_u32(const void* p) {
    uint32_t a;
    asm("{ .reg .u64 t; cvta.to.shared.u64 t, %1; cvt.u32.u64 %0, t; }" : "=r"(a) : "l"(p));
    return a;
}
__device__ __forceinline__ void cp16(uint32_t dst, const void* src) {
    asm volatile("cp.async.cg.shared.global [%0], [%1], 16;" :: "r"(dst), "l"(src));
}
__device__ __forceinline__ void cp_commit() { asm volatile("cp.async.commit_group;" ::: "memory"); }
template<int N> __device__ __forceinline__ void cp_wait() {
    asm volatile("cp.async.wait_group %0;" :: "n"(N) : "memory");
}
__device__ __forceinline__ void ldsm4(uint32_t& r0, uint32_t& r1, uint32_t& r2, uint32_t& r3,
                                      uint32_t addr) {
    asm volatile("ldmatrix.sync.aligned.m8n8.x4.shared.b16 {%0,%1,%2,%3}, [%4];"
                 : "=r"(r0), "=r"(r1), "=r"(r2), "=r"(r3) : "r"(addr));
}
__device__ __forceinline__ void ldsm4t(uint32_t& r0, uint32_t& r1, uint32_t& r2, uint32_t& r3,
                                       uint32_t addr) {
    asm volatile("ldmatrix.sync.aligned.m8n8.x4.trans.shared.b16 {%0,%1,%2,%3}, [%4];"
                 : "=r"(r0), "=r"(r1), "=r"(r2), "=r"(r3) : "r"(addr));
}
__device__ __forceinline__ void mma16816(float* c, const uint32_t* a,
                                         uint32_t b0, uint32_t b1) {
    asm volatile(
        "mma.sync.aligned.m16n8k16.row.col.f32.bf16.bf16.f32 "
        "{%0,%1,%2,%3}, {%4,%5,%6,%7}, {%8,%9}, {%0,%1,%2,%3};"
        : "+f"(c[0]), "+f"(c[1]), "+f"(c[2]), "+f"(c[3])
        : "r"(a[0]), "r"(a[1]), "r"(a[2]), "r"(a[3]), "r"(b0), "r"(b1));
}
__device__ __forceinline__ uint32_t swz(uint32_t o) { return o ^ ((o >> 3) & 0x70); }
__device__ __forceinline__ uint32_t packbf(float x, float y) {
    __nv_bfloat162 h = __floats2bfloat162_rn(x, y);
    return *(uint32_t*)&h;
}
__device__ __forceinline__ float tanha(float x) {
    float y;
    asm("tanh.approx.f32 %0, %1;" : "=f"(y) : "f"(x));
    return y;
}

// ---------------- ada: silu(c) @ ada_w^T + ada_b (silu fused) ----------------
__global__ void ada_kernel(const float* __restrict__ c_in,
                           const float* __restrict__ ada_w,
                           const float* __restrict__ ada_b) {
    const int warp = threadIdx.x >> 5, lane = threadIdx.x & 31;
    const int j = blockIdx.x * 4 + warp;
    const int n = blockIdx.y;
    const float* wrow = ada_w + (size_t)j * C_;
    const float* crow = c_in + n * C_;
    float s = 0.f;
    for (int k = lane; k < C_; k += 32) {
        float cv = crow[k];
        s += (cv / (1.f + __expf(-cv))) * wrow[k];
    }
    #pragma unroll
    for (int o = 16; o > 0; o >>= 1) s += __shfl_xor_sync(0xffffffffu, s, o);
    if (lane == 0) g_ada[n*ADA6 + j] = s + ada_b[j];
}

// ---------------- merged weight conversion fp32 -> bf16 ----------------
#define NW0 (3*C_*C_)
#define NW1 (C_*C_)
#define NW2 (HID*C_)
#define NW3 (C_*HID)
__global__ void f2bf_all(const float* __restrict__ s0, const float* __restrict__ s1,
                         const float* __restrict__ s2, const float* __restrict__ s3) {
    int i = (blockIdx.x * blockDim.x + threadIdx.x) * 4;
    const float* s;
    __nv_bfloat16* d;
    int off;
    if (i < NW0)                 { s = s0; d = g_wqkv; off = i; }
    else if (i < NW0+NW1)        { s = s1; d = g_wproj; off = i - NW0; }
    else if (i < NW0+NW1+NW2)    { s = s2; d = g_wfc1;  off = i - NW0 - NW1; }
    else if (i < NW0+NW1+NW2+NW3){ s = s3; d = g_wfc2;  off = i - NW0 - NW1 - NW2; }
    else return;
    float4 v = *(const float4*)(s + off);
    ((__nv_bfloat162*)(d + off))[0] = __floats2bfloat162_rn(v.x, v.y);
    ((__nv_bfloat162*)(d + off))[1] = __floats2bfloat162_rn(v.z, v.w);
}

// ---------------- LayerNorm + adaLN modulation -> bf16 (vectorized) ----------------
// 192 threads, float4 per thread, 8B stores.
template<int SEQ>
__global__ void __launch_bounds__(192) ln_mod_kernel(const float* __restrict__ xin) {
    const int t = blockIdx.x;
    const int tid = threadIdx.x;
    const int wid = tid >> 5, lane = tid & 31;
    int n;
    const float* xr;
    if (SEQ) {
        n = t >> 12;
        xr = g_xnew + (size_t)t * C_;
    } else {
        const int win = t >> 6, tw = t & 63;
        n = win >> 6;
        const int wi = win & 63;
        const int gi = ((wi >> 3) << 3) + (tw >> 3);
        const int gj = ((wi & 7) << 3) + (tw & 7);
        const int i0 = (gi + 4) & 63, j0 = (gj + 4) & 63;
        xr = xin + (((size_t)n << 12) + (i0 << 6) + j0) * C_;
    }
    const int cix = tid * 4;
    float4 v = *(const float4*)(xr + cix);
    float s  = v.x + v.y + v.z + v.w;
    float ss = v.x*v.x + v.y*v.y + v.z*v.z + v.w*v.w;
    __shared__ float red[14];
    #pragma unroll
    for (int o = 16; o > 0; o >>= 1) {
        s  += __shfl_xor_sync(0xffffffffu, s,  o);
        ss += __shfl_xor_sync(0xffffffffu, ss, o);
    }
    if (lane == 0) { red[wid] = s; red[6 + wid] = ss; }
    __syncthreads();
    if (tid == 0) {
        float a = 0.f, b = 0.f;
        #pragma unroll
        for (int w = 0; w < 6; w++) { a += red[w]; b += red[6 + w]; }
        const float mean = a * (1.f / 768.f);
        const float var  = b * (1.f / 768.f) - mean * mean;
        red[12] = mean;
        red[13] = rsqrtf(var + 1e-6f);
    }
    __syncthreads();
    const float mean = red[12], rstd = red[13];
    const float4 sc = *(const float4*)(g_ada + n*ADA6 + (SEQ ? 4 : 1) * C_ + cix);
    const float4 sh = *(const float4*)(g_ada + n*ADA6 + (SEQ ? 3 : 0) * C_ + cix);
    uint2 o;
    o.x = packbf((v.x - mean) * rstd * (1.f + sc.x) + sh.x,
                 (v.y - mean) * rstd * (1.f + sc.y) + sh.y);
    o.y = packbf((v.z - mean) * rstd * (1.f + sc.z) + sh.z,
                 (v.w - mean) * rstd * (1.f + sc.w) + sh.w);
    *(uint2*)(g_actA + (size_t)t * C_ + cix) = o;
}

// ---------------- HMMA bf16 GEMM: C[m,n] = sum_k A[m,k]*W[n,k] ----------------
// CTA 128x256, 8 warps (2x4), warp tile 64x64. 4-deep smem ring, reg double buffer.
#define BM 128
#define BN 256
#define BUFB ((BM + BN) * 128)
#define GEMM_SMEM (4 * BUFB)

template<int MODE>
__global__ void __launch_bounds__(256, 1) gemm_tc(
    const float* __restrict__ bias,
    const float* __restrict__ x_seq,
    float* __restrict__ dout)
{
    constexpr int K   = (MODE == 3) ? HID : C_;
    constexpr int NCH = K / KC;
    const __nv_bfloat16* A = (MODE == 3) ? g_actB : g_actA;
    const __nv_bfloat16* W = (MODE == 0) ? g_wqkv : (MODE == 1) ? g_wproj
                           : (MODE == 2) ? g_wfc1 : g_wfc2;

    extern __shared__ char smem[];
    const uint32_t s0 = smem_u32(smem);
    const int tid = threadIdx.x;
    const int wid = tid >> 5, lane = tid & 31;
    const int bm = blockIdx.y * BM, bn = blockIdx.x * BN;

    const __nv_bfloat16* Brow = W + (size_t)(bn + tid) * K;
    const __nv_bfloat16* Arow = A + (size_t)(bm + (tid & 127)) * K;
    uint32_t bofs[8], aofs[8];
    #pragma unroll
    for (int s = 0; s < 8; s++) {
        bofs[s] = 16384u + swz((uint32_t)tid * 128 + s * 16);
        aofs[s] = swz((uint32_t)(tid & 127) * 128 + s * 16);
    }
    auto load_chunk = [&](int i) {
        const uint32_t buf = s0 + (uint32_t)(i & 3) * BUFB;
        const __nv_bfloat16* bsrc = Brow + i * KC;
        #pragma unroll
        for (int s = 0; s < 8; s++) cp16(buf + bofs[s], bsrc + s * 8);
        if (tid < 128) {
            const __nv_bfloat16* asrc = Arow + i * KC;
            #pragma unroll
            for (int s = 0; s < 8; s++) cp16(buf + aofs[s], asrc + s * 8);
        }
        cp_commit();
    };
    load_chunk(0); load_chunk(1); load_chunk(2);

    const int wm = wid >> 2, wn = wid & 3;
    uint32_t aOff[4], aXor[4];
    #pragma unroll
    for (int mi = 0; mi < 4; mi++) {
        const int r = wm * 64 + mi * 16 + (lane & 15);
        aOff[mi] = (uint32_t)r * 128 + ((lane >> 4) << 4);
        aXor[mi] = ((uint32_t)(r & 7)) << 4;
    }
    uint32_t bOff[4], bXor[4];
    #pragma unroll
    for (int nj = 0; nj < 4; nj++) {
        const int r = wn * 64 + nj * 16 + (lane & 15);
        bOff[nj] = 16384u + (uint32_t)r * 128 + ((lane >> 4) << 4);
        bXor[nj] = ((uint32_t)(r & 7)) << 4;
    }

    uint32_t aR[2][4][4], bR[2][4][4];
    auto do_ldsm = [&](uint32_t buf, int ks, int p) {
        const uint32_t kb = (uint32_t)ks * 32;
        #pragma unroll
        for (int mi = 0; mi < 4; mi++)
            ldsm4(aR[p][mi][0], aR[p][mi][1], aR[p][mi][2], aR[p][mi][3],
                  buf + (aOff[mi] & ~0x70u) + (((aOff[mi] & 0x70u) + kb) ^ aXor[mi]));
        #pragma unroll
        for (int nj = 0; nj < 4; nj++)
            ldsm4(bR[p][nj][0], bR[p][nj][1], bR[p][nj][2], bR[p][nj][3],
                  buf + (bOff[nj] & ~0x70u) + (((bOff[nj] & 0x70u) + kb) ^ bXor[nj]));
    };

    float acc[4][8][4];
    #pragma unroll
    for (int mi = 0; mi < 4; mi++)
        #pragma unroll
        for (int ni = 0; ni < 8; ni++)
            #pragma unroll
            for (int e = 0; e < 4; e++) acc[mi][ni][e] = 0.f;

    cp_wait<2>();
    __syncthreads();
    do_ldsm(s0, 0, 0);

    for (int i = 0; i < NCH; i++) {
        const uint32_t buf = s0 + (uint32_t)(i & 3) * BUFB;
        #pragma unroll
        for (int ks = 0; ks < 4; ks++) {
            const int p = ks & 1;
            if (ks < 3) {
                do_ldsm(buf, ks + 1, p ^ 1);
            } else if (i + 1 < NCH) {
                if (i + 2 < NCH) cp_wait<1>(); else cp_wait<0>();
                __syncthreads();
                if (i + 3 < NCH) load_chunk(i + 3);
                do_ldsm(s0 + (uint32_t)((i + 1) & 3) * BUFB, 0, p ^ 1);
            }
            #pragma unroll
            for (int mi = 0; mi < 4; mi++) {
                #pragma unroll
                for (int nj = 0; nj < 4; nj++) {
                    mma16816(acc[mi][nj*2+0], aR[p][mi], bR[p][nj][0], bR[p][nj][2]);
                    mma16816(acc[mi][nj*2+1], aR[p][mi], bR[p][nj][1], bR[p][nj][3]);
                }
            }
        }
    }

    // ---------------- epilogue ----------------
    const int rIn = lane >> 2;
    const int cIn = (lane & 3) * 2;
    #pragma unroll
    for (int mi = 0; mi < 4; mi++) {
        #pragma unroll
        for (int h = 0; h < 2; h++) {
            const int row = bm + wm * 64 + mi * 16 + rIn + h * 8;
            if constexpr (MODE == 0) {
                const int win = row >> 6, tw = row & 63;
                #pragma unroll
                for (int ni = 0; ni < 8; ni++) {
                    const int g = bn + wn * 64 + ni * 8 + cIn;
                    const int which = g / 768;
                    const int head = (g >> 6) % 12;
                    const int d0 = g & 63;
                    __nv_bfloat16* dst = g_qkv + (size_t)which * REGSZ
                               + (((size_t)(win * NHEAD + head)) << 12) + (tw << 6) + d0;
                    *(__nv_bfloat162*)dst = __floats2bfloat162_rn(
                        acc[mi][ni][h*2+0] + __ldg(bias + g),
                        acc[mi][ni][h*2+1] + __ldg(bias + g + 1));
                }
            } else if constexpr (MODE == 1) {
                const int win = row >> 6, tw = row & 63;
                const int n = win >> 6, wi = win & 63;
                const int gi = ((wi >> 3) << 3) + (tw >> 3);
                const int gj = ((wi & 7) << 3) + (tw & 7);
                const int i0 = (gi + 4) & 63, j0 = (gj + 4) & 63;
                const size_t srow = ((size_t)n << 12) + (i0 << 6) + j0;
                const float* xr = x_seq + srow * C_;
                float* dst = g_xnew + srow * C_;
                const float* gp = g_ada + n * ADA6 + 2 * C_;
                #pragma unroll
                for (int ni = 0; ni < 8; ni++) {
                    const int g = bn + wn * 64 + ni * 8 + cIn;
                    float2 v;
                    v.x = xr[g]   + gp[g]   * (acc[mi][ni][h*2+0] + __ldg(bias + g));
                    v.y = xr[g+1] + gp[g+1] * (acc[mi][ni][h*2+1] + __ldg(bias + g + 1));
                    *(float2*)(dst + g) = v;
                }
            } else if constexpr (MODE == 2) {
                __nv_bfloat16* dst = g_actB + (size_t)row * HID;
                #pragma unroll
                for (int ni = 0; ni < 8; ni++) {
                    const int g = bn + wn * 64 + ni * 8 + cIn;
                    float u0 = acc[mi][ni][h*2+0] + __ldg(bias + g);
                    float u1 = acc[mi][ni][h*2+1] + __ldg(bias + g + 1);
                    float t0 = tanha(0.7978845608028654f * (u0 + 0.044715f * u0 * u0 * u0));
                    float t1 = tanha(0.7978845608028654f * (u1 + 0.044715f * u1 * u1 * u1));
                    *(__nv_bfloat162*)(dst + g) =
                        __floats2bfloat162_rn(0.5f * u0 * (1.f + t0), 0.5f * u1 * (1.f + t1));
                }
            } else {
                const int n = row >> 12;
                const float* xr = g_xnew + (size_t)row * C_;
                const float* gp = g_ada + n * ADA6 + 5 * C_;
                float* dst = dout + (size_t)row * C_;
                #pragma unroll
                for (int ni = 0; ni < 8; ni++) {
                    const int g = bn + wn * 64 + ni * 8 + cIn;
                    float2 v;
                    v.x = xr[g]   + gp[g]   * (acc[mi][ni][h*2+0] + __ldg(bias + g));
                    v.y = xr[g+1] + gp[g+1] * (acc[mi][ni][h*2+1] + __ldg(bias + g + 1));
                    *(float2*)(dst + g) = v;
                }
            }
        }
    }
}

// ---------------- HMMA window attention: 2 heads per CTA, 256 threads ----------------
__global__ void __launch_bounds__(256) attn_hmma() {
    __shared__ __align__(1024) __nv_bfloat16 sm[2 * 3 * 4096];  // [head][q|k|v]
    const uint32_t sb = smem_u32(sm);
    const int bid = blockIdx.x;                 // win*6 + head_pair
    const int win = bid / 6, hp = bid - 6 * win;
    const int tid = threadIdx.x, wid = tid >> 5, lane = tid & 31;

    // loads: tid<128 -> head 2*hp, else head 2*hp+1
    {
        const int hh = tid >> 7;
        const int t0 = tid & 127;
        const __nv_bfloat16* qb = g_qkv + (size_t)(win * NHEAD + hp * 2 + hh) * 4096;
        const uint32_t hsb = sb + (uint32_t)hh * 24576u;
        const int r = t0 & 63;
        const __nv_bfloat16* src = ((t0 < 64) ? qb : (qb + REGSZ)) + r * 64;
        const uint32_t base = hsb + ((t0 < 64) ? 0u : 8192u);
        #pragma unroll
        for (int s = 0; s < 8; s++)
            cp16(base + swz((uint32_t)r * 128 + s * 16), src + s * 8);
        const __nv_bfloat16* vb = qb + 2 * REGSZ;
        const int vr = t0 >> 1;
        const int c0 = (t0 & 1) * 4;
        #pragma unroll
        for (int s = 0; s < 4; s++)
            cp16(hsb + 16384u + swz((uint32_t)vr * 128 + (c0 + s) * 16),
                 vb + vr * 64 + (c0 + s) * 8);
    }
    cp_commit();
    cp_wait<0>();
    __syncthreads();

    // compute: warps 0-3 head 0, warps 4-7 head 1; w4 = warp-within-head
    const int hw = wid >> 2, w4 = wid & 3;
    const uint32_t hsb = sb + (uint32_t)hw * 24576u;
    const int head = hp * 2 + hw;
    const int lr = lane & 15, lc = lane >> 4;

    uint32_t aF[4][4];
    #pragma unroll
    for (int ks = 0; ks < 4; ks++)
        ldsm4(aF[ks][0], aF[ks][1], aF[ks][2], aF[ks][3],
              hsb + swz((uint32_t)(16 * w4 + lr) * 128 + lc * 16 + ks * 32));

    float S[8][4];
    #pragma unroll
    for (int f = 0; f < 8; f++)
        #pragma unroll
        for (int e = 0; e < 4; e++) S[f][e] = 0.f;

    #pragma unroll
    for (int nj = 0; nj < 4; nj++) {
        #pragma unroll
        for (int ks = 0; ks < 4; ks++) {
            uint32_t b0, b1, b2, b3;
            ldsm4(b0, b1, b2, b3,
                  hsb + 8192u + swz((uint32_t)(nj * 16 + lr) * 128 + lc * 16 + ks * 32));
            mma16816(S[2*nj+0], aF[ks], b0, b2);
            mma16816(S[2*nj+1], aF[ks], b1, b3);
        }
    }

    float mx0 = -1e30f, mx1 = -1e30f;
    #pragma unroll
    for (int f = 0; f < 8; f++) {
        #pragma unroll
        for (int e = 0; e < 4; e++) S[f][e] *= 0.125f;
        mx0 = fmaxf(mx0, fmaxf(S[f][0], S[f][1]));
        mx1 = fmaxf(mx1, fmaxf(S[f][2], S[f][3]));
    }
    mx0 = fmaxf(mx0, __shfl_xor_sync(0xffffffffu, mx0, 1));
    mx0 = fmaxf(mx0, __shfl_xor_sync(0xffffffffu, mx0, 2));
    mx1 = fmaxf(mx1, __shfl_xor_sync(0xffffffffu, mx1, 1));
    mx1 = fmaxf(mx1, __shfl_xor_sync(0xffffffffu, mx1, 2));
    float sm0 = 0.f, sm1 = 0.f;
    #pragma unroll
    for (int f = 0; f < 8; f++) {
        S[f][0] = __expf(S[f][0] - mx0); sm0 += S[f][0];
        S[f][1] = __expf(S[f][1] - mx0); sm0 += S[f][1];
        S[f][2] = __expf(S[f][2] - mx1); sm1 += S[f][2];
        S[f][3] = __expf(S[f][3] - mx1); sm1 += S[f][3];
    }
    sm0 += __shfl_xor_sync(0xffffffffu, sm0, 1);
    sm0 += __shfl_xor_sync(0xffffffffu, sm0, 2);
    sm1 += __shfl_xor_sync(0xffffffffu, sm1, 1);
    sm1 += __shfl_xor_sync(0xffffffffu, sm1, 2);
    const float iv0 = 1.f / sm0, iv1 = 1.f / sm1;
    #pragma unroll
    for (int f = 0; f < 8; f++) {
        S[f][0] *= iv0; S[f][1] *= iv0; S[f][2] *= iv1; S[f][3] *= iv1;
    }

    uint32_t aP[4][4];
    #pragma unroll
    for (int ks = 0; ks < 4; ks++) {
        aP[ks][0] = packbf(S[2*ks+0][0], S[2*ks+0][1]);
        aP[ks][1] = packbf(S[2*ks+0][2], S[2*ks+0][3]);
        aP[ks][2] = packbf(S[2*ks+1][0], S[2*ks+1][1]);
        aP[ks][3] = packbf(S[2*ks+1][2], S[2*ks+1][3]);
    }

    float O[8][4];
    #pragma unroll
    for (int f = 0; f < 8; f++)
        #pragma unroll
        for (int e = 0; e < 4; e++) O[f][e] = 0.f;
    #pragma unroll
    for (int ks = 0; ks < 4; ks++) {
        #pragma unroll
        for (int nj = 0; nj < 4; nj++) {
            uint32_t r0, r1, r2, r3;
            ldsm4t(r0, r1, r2, r3,
                   hsb + 16384u + swz((uint32_t)(16 * ks + lr) * 128 + (2 * nj + lc) * 16));
            mma16816(O[2*nj+0], aP[ks], r0, r1);
            mma16816(O[2*nj+1], aP[ks], r2, r3);
        }
    }

    const int r0row = 16 * w4 + (lane >> 2);
    const int q2 = (lane & 3) * 2;
    #pragma unroll
    for (int f = 0; f < 8; f++) {
        __nv_bfloat16* d0 = g_actA + (size_t)(win * 64 + r0row) * C_ + head * 64 + 8 * f + q2;
        *(__nv_bfloat162*)d0 = __floats2bfloat162_rn(O[f][0], O[f][1]);
        *(__nv_bfloat162*)(d0 + 8 * C_) = __floats2bfloat162_rn(O[f][2], O[f][3]);
    }
}

// ---------------- launcher ----------------
extern "C" void kernel_launch(void* const* d_in, const int* in_sizes, int n_in,
                              void* d_out, int out_size) {
    const float* x_seq  = (const float*)d_in[0];
    const float* c_in   = (const float*)d_in[1];
    const float* qkv_w  = (const float*)d_in[2];
    const float* qkv_b  = (const float*)d_in[3];
    const float* proj_w = (const float*)d_in[4];
    const float* proj_b = (const float*)d_in[5];
    const float* fc1_w  = (const float*)d_in[6];
    const float* fc1_b  = (const float*)d_in[7];
    const float* fc2_w  = (const float*)d_in[8];
    const float* fc2_b  = (const float*)d_in[9];
    const float* ada_w  = (const float*)d_in[10];
    const float* ada_b  = (const float*)d_in[11];
    float* out = (float*)d_out;

    cudaFuncSetAttribute(gemm_tc<0>, cudaFuncAttributeMaxDynamicSharedMemorySize, GEMM_SMEM);
    cudaFuncSetAttribute(gemm_tc<1>, cudaFuncAttributeMaxDynamicSharedMemorySize, GEMM_SMEM);
    cudaFuncSetAttribute(gemm_tc<2>, cudaFuncAttributeMaxDynamicSharedMemorySize, GEMM_SMEM);
    cudaFuncSetAttribute(gemm_tc<3>, cudaFuncAttributeMaxDynamicSharedMemorySize, GEMM_SMEM);

    constexpr int NWTOT = NW0 + NW1 + NW2 + NW3;

    ada_kernel<<<dim3(ADA6/4, NB), 128>>>(c_in, ada_w, ada_b);          // 1
    f2bf_all<<<(NWTOT/4 + 255)/256, 256>>>(qkv_w, proj_w, fc1_w, fc2_w); // 2
    ln_mod_kernel<0><<<M_TOT, 192>>>(x_seq);                            // 3
    gemm_tc<0><<<dim3(9, 256), 256, GEMM_SMEM>>>(qkv_b, nullptr, nullptr);  // 4
    attn_hmma<<<512*6, 256>>>();                                        // 5
    gemm_tc<1><<<dim3(3, 256), 256, GEMM_SMEM>>>(proj_b, x_seq, nullptr);   // 6 <- ncu
    ln_mod_kernel<1><<<M_TOT, 192>>>(nullptr);                          // 7
    gemm_tc<2><<<dim3(12, 256), 256, GEMM_SMEM>>>(fc1_b, nullptr, nullptr); // 8
    gemm_tc<3><<<dim3(3, 256), 256, GEMM_SMEM>>>(fc2_b, nullptr, out);      // 9
}